// round 1
// baseline (speedup 1.0000x reference)
#include <cuda_runtime.h>

// Problem constants (fixed by setup_inputs)
#define B_  4
#define T_  1024
#define C_  1024
#define H_  16
#define DH  64
#define MAXREL 32

// Scratch (allocation-free rule: __device__ globals)
__device__ float g_Q[B_*H_*T_*DH];
__device__ float g_K[B_*H_*T_*DH];
__device__ float g_V[B_*H_*T_*DH];
__device__ float g_att[B_*T_*C_];

// ---------------------------------------------------------------------------
// GEMM: C = A[M,K] @ W[N,K]^T + bias[N]
// MODE 0: C row-major [M,N]
// MODE 1: C written as [B,H,T,DH]  (m = b*T+t, n = h*DH+d)
// Tiles: BM=BN=128, BK=8, 256 threads, 8x8 per-thread register tile.
// M=4096, N=1024, K=1024 hardcoded (all divisible).
// ---------------------------------------------------------------------------
template<int MODE>
__global__ void __launch_bounds__(256)
gemm_xwT(const float* __restrict__ A, const float* __restrict__ W,
         const float* __restrict__ bias, float* __restrict__ C)
{
    const int N = 1024, K = 1024;
    const int BK = 8;
    __shared__ float As[BK][128];
    __shared__ float Bs[BK][128];

    int tid = threadIdx.x;
    int tx = tid & 15, ty = tid >> 4;
    int m0 = blockIdx.y * 128, n0 = blockIdx.x * 128;
    int lrow = tid >> 1;          // 0..127
    int lcol = (tid & 1) * 4;     // 0 or 4

    float acc[8][8];
#pragma unroll
    for (int i = 0; i < 8; i++)
#pragma unroll
        for (int j = 0; j < 8; j++) acc[i][j] = 0.f;

    const float* Ap = A + (size_t)(m0 + lrow) * K + lcol;
    const float* Wp = W + (size_t)(n0 + lrow) * K + lcol;

    for (int k0 = 0; k0 < K; k0 += BK) {
        float4 a = *(const float4*)(Ap + k0);
        float4 b = *(const float4*)(Wp + k0);
        As[lcol + 0][lrow] = a.x; As[lcol + 1][lrow] = a.y;
        As[lcol + 2][lrow] = a.z; As[lcol + 3][lrow] = a.w;
        Bs[lcol + 0][lrow] = b.x; Bs[lcol + 1][lrow] = b.y;
        Bs[lcol + 2][lrow] = b.z; Bs[lcol + 3][lrow] = b.w;
        __syncthreads();
#pragma unroll
        for (int kk = 0; kk < BK; kk++) {
            float4 a0 = *(const float4*)&As[kk][ty * 8];
            float4 a1 = *(const float4*)&As[kk][ty * 8 + 4];
            float4 b0 = *(const float4*)&Bs[kk][tx * 8];
            float4 b1 = *(const float4*)&Bs[kk][tx * 8 + 4];
            float ra[8] = {a0.x, a0.y, a0.z, a0.w, a1.x, a1.y, a1.z, a1.w};
            float rb[8] = {b0.x, b0.y, b0.z, b0.w, b1.x, b1.y, b1.z, b1.w};
#pragma unroll
            for (int i = 0; i < 8; i++)
#pragma unroll
                for (int j = 0; j < 8; j++)
                    acc[i][j] += ra[i] * rb[j];
        }
        __syncthreads();
    }

    int n_base = n0 + tx * 8;
    float bj[8];
#pragma unroll
    for (int j = 0; j < 8; j++) bj[j] = bias[n_base + j];

#pragma unroll
    for (int i = 0; i < 8; i++) {
        int m = m0 + ty * 8 + i;
        float v[8];
#pragma unroll
        for (int j = 0; j < 8; j++) v[j] = acc[i][j] + bj[j];
        float* dst;
        if (MODE == 0) {
            dst = C + (size_t)m * N + n_base;
        } else {
            int b_ = m >> 10, t = m & 1023;
            int h = n_base >> 6, d = n_base & 63;   // 8 cols never cross a head
            dst = C + ((((size_t)b_ * H_ + h) * T_ + t) * DH + d);
        }
        *(float4*)dst       = make_float4(v[0], v[1], v[2], v[3]);
        *(float4*)(dst + 4) = make_float4(v[4], v[5], v[6], v[7]);
    }
}

// ---------------------------------------------------------------------------
// Fused causal "algebraic" attention. One pass (normalization is linear):
//   w = relu(qk*scale + bias)+1e-6 on kept (k<=q) positions
//   out = (sum_k w*V) / (sum_k w + 1e-6)
// Block = one (b, h, 64-row q tile). 256 threads; two 64x64x64 smem GEMMs
// per k-tile (4x4 register micro-tiles).
// ---------------------------------------------------------------------------
struct AttnSmem {
    float Qst[64][64];   // [d][q]
    float Kst[64][64];   // [d][k]
    float Vs [64][64];   // [k][d]
    float Ws [64][65];   // [q][k]  (padded)
    float bh [64];
    float rs [64];
};

__global__ void __launch_bounds__(256)
attn_kernel(const float* __restrict__ Q, const float* __restrict__ K,
            const float* __restrict__ V, const float* __restrict__ rel_bias,
            float* __restrict__ out)
{
    extern __shared__ char smem_raw[];
    AttnSmem& S = *reinterpret_cast<AttnSmem*>(smem_raw);

    const int qt = blockIdx.x;   // 0..15
    const int h  = blockIdx.y;   // 0..15
    const int b  = blockIdx.z;   // 0..3
    const int tid = threadIdx.x;
    const int tx = tid & 15, ty = tid >> 4;
    const float scale = 0.125f;  // 64^-0.5

    const float* Qg = Q + (((size_t)b * H_ + h) * T_ + qt * 64) * DH;

    if (tid < 2 * MAXREL - 1) S.bh[tid] = rel_bias[tid * H_ + h];

    // Load Q tile transposed into smem: [d][q]
    {
        int q = tid >> 2, d0 = (tid & 3) * 16;
        const float* src = Qg + q * DH + d0;
#pragma unroll
        for (int i = 0; i < 16; i++) S.Qst[d0 + i][q] = src[i];
    }

    float acc[4][4];
    float rsum[4] = {0.f, 0.f, 0.f, 0.f};
#pragma unroll
    for (int i = 0; i < 4; i++)
#pragma unroll
        for (int j = 0; j < 4; j++) acc[i][j] = 0.f;

    __syncthreads();

    const int q0 = qt * 64;
    for (int kt = 0; kt <= qt; kt++) {
        const int k0 = kt * 64;
        const float* Kg = K + (((size_t)b * H_ + h) * T_ + k0) * DH;
        const float* Vg = V + (((size_t)b * H_ + h) * T_ + k0) * DH;
        {
            int k = tid >> 2, d0 = (tid & 3) * 16;
            const float* ks = Kg + k * DH + d0;
#pragma unroll
            for (int i = 0; i < 16; i++) S.Kst[d0 + i][k] = ks[i];
            const float4* vsrc = (const float4*)(Vg + k * DH + d0);
            float4* vdst = (float4*)(&S.Vs[k][d0]);
#pragma unroll
            for (int i = 0; i < 4; i++) vdst[i] = vsrc[i];
        }
        __syncthreads();

        // GEMM1: S[q][k] = sum_d Q[q][d]*K[k][d]
        float s[4][4];
#pragma unroll
        for (int i = 0; i < 4; i++)
#pragma unroll
            for (int j = 0; j < 4; j++) s[i][j] = 0.f;
#pragma unroll
        for (int d = 0; d < 64; d++) {
            float4 qv = *(const float4*)&S.Qst[d][ty * 4];
            float4 kv = *(const float4*)&S.Kst[d][tx * 4];
            float qa[4] = {qv.x, qv.y, qv.z, qv.w};
            float ka[4] = {kv.x, kv.y, kv.z, kv.w};
#pragma unroll
            for (int i = 0; i < 4; i++)
#pragma unroll
                for (int j = 0; j < 4; j++)
                    s[i][j] += qa[i] * ka[j];
        }

        // scale + clipped rel bias + causal mask + relu + 1e-6
#pragma unroll
        for (int i = 0; i < 4; i++) {
            int qg = q0 + ty * 4 + i;
#pragma unroll
            for (int j = 0; j < 4; j++) {
                int kg = k0 + tx * 4 + j;
                float w = 0.f;
                if (kg <= qg) {
                    int rel = kg - qg;                      // <= 0
                    int u = rel < -(MAXREL - 1) ? 0 : rel + (MAXREL - 1);
                    float v = fmaf(s[i][j], scale, S.bh[u]);
                    w = fmaxf(v, 0.f) + 1e-6f;
                }
                S.Ws[ty * 4 + i][tx * 4 + j] = w;
            }
        }
        __syncthreads();

        // GEMM2: acc[q][d] += W[q][k]*V[k][d]; rsum[q] += W[q][k]
#pragma unroll
        for (int k = 0; k < 64; k++) {
            float4 vv = *(const float4*)&S.Vs[k][tx * 4];
            float va[4] = {vv.x, vv.y, vv.z, vv.w};
#pragma unroll
            for (int i = 0; i < 4; i++) {
                float w = S.Ws[ty * 4 + i][k];
                if (tx == 0) rsum[i] += w;
#pragma unroll
                for (int j = 0; j < 4; j++)
                    acc[i][j] += w * va[j];
            }
        }
        __syncthreads();
    }

    if (tx == 0) {
#pragma unroll
        for (int i = 0; i < 4; i++) S.rs[ty * 4 + i] = rsum[i];
    }
    __syncthreads();

    // out layout [B,T,H,DH] == row-major [4096,1024] for the final GEMM
#pragma unroll
    for (int i = 0; i < 4; i++) {
        int q = q0 + ty * 4 + i;
        float inv = 1.f / (S.rs[ty * 4 + i] + 1e-6f);
        float* dst = out + (((size_t)b * T_ + q) * H_ + h) * DH + tx * 4;
        *(float4*)dst = make_float4(acc[i][0] * inv, acc[i][1] * inv,
                                    acc[i][2] * inv, acc[i][3] * inv);
    }
}

// ---------------------------------------------------------------------------
extern "C" void kernel_launch(void* const* d_in, const int* in_sizes, int n_in,
                              void* d_out, int out_size)
{
    const float* x   = (const float*)d_in[0];
    // d_in[1] = mask (tril, deterministic) — causality is hardcoded
    const float* Wq  = (const float*)d_in[2];
    const float* bq  = (const float*)d_in[3];
    const float* Wk  = (const float*)d_in[4];
    const float* bk  = (const float*)d_in[5];
    const float* Wv  = (const float*)d_in[6];
    const float* bv  = (const float*)d_in[7];
    const float* Wo  = (const float*)d_in[8];
    const float* bo  = (const float*)d_in[9];
    const float* rel = (const float*)d_in[10];
    // d_in[11] = n_head (16, hardcoded)

    float *pQ, *pK, *pV, *pA;
    cudaGetSymbolAddress((void**)&pQ, g_Q);
    cudaGetSymbolAddress((void**)&pK, g_K);
    cudaGetSymbolAddress((void**)&pV, g_V);
    cudaGetSymbolAddress((void**)&pA, g_att);

    dim3 gg(C_ / 128, (B_ * T_) / 128);  // (8, 32)
    gemm_xwT<1><<<gg, 256>>>(x, Wq, bq, pQ);
    gemm_xwT<1><<<gg, 256>>>(x, Wk, bk, pK);
    gemm_xwT<1><<<gg, 256>>>(x, Wv, bv, pV);

    int smem = (int)sizeof(AttnSmem);
    cudaFuncSetAttribute(attn_kernel, cudaFuncAttributeMaxDynamicSharedMemorySize, smem);
    attn_kernel<<<dim3(T_ / 64, H_, B_), 256, smem>>>(pQ, pK, pV, rel, pA);

    gemm_xwT<0><<<gg, 256>>>(pA, Wo, bo, (float*)d_out);
}

// round 2
// speedup vs baseline: 1.8343x; 1.8343x over previous
#include <cuda_runtime.h>

// Problem constants (fixed by setup_inputs)
#define B_  4
#define T_  1024
#define C_  1024
#define H_  16
#define DH  64
#define MAXREL 32

// Scratch (allocation-free rule: __device__ globals)
__device__ float g_Q[B_*H_*T_*DH];
__device__ float g_K[B_*H_*T_*DH];
__device__ float g_V[B_*H_*T_*DH];
__device__ float g_att[B_*T_*C_];

__device__ __forceinline__ unsigned f2tf32(float x) {
    unsigned r;
    asm("cvt.rna.tf32.f32 %0, %1;" : "=r"(r) : "f"(x));
    return r;
}

// ---------------------------------------------------------------------------
// Tensor-core GEMM: C = A[M,K] @ W[N,K]^T + bias[N], tf32 mma, fp32 accum.
// MODE 0: C row-major [M,N]        MODE 1: C written as [B,H,T,DH]
// Tiles: BM=BN=128, BK=16, 256 threads (8 warps as 2x4), warp tile 64x32.
// Per k8-step: 4 A-frags + 4 B-frags -> 16 mma.m16n8k8.
// smem rows use stride 20: (r*20 mod 32) covers {0,4,...,28} exactly, so
// fragment LDS (8 rows x 4 cols per instruction) is bank-conflict-free.
// M=4096, N=1024, K=1024 hardcoded.
// ---------------------------------------------------------------------------
#define SSTR 20

__device__ __forceinline__ void sts_tile(unsigned* S, int row, int cg, float4 v) {
    S[row * SSTR + cg + 0] = f2tf32(v.x);
    S[row * SSTR + cg + 1] = f2tf32(v.y);
    S[row * SSTR + cg + 2] = f2tf32(v.z);
    S[row * SSTR + cg + 3] = f2tf32(v.w);
}

template<int MODE>
__global__ void __launch_bounds__(256, 2)
gemm_tc(const float* __restrict__ A, const float* __restrict__ W,
        const float* __restrict__ bias, float* __restrict__ C)
{
    const int K = 1024, N = 1024;
    __shared__ unsigned As[2][128 * SSTR];
    __shared__ unsigned Bs[2][128 * SSTR];

    const int t = threadIdx.x;
    const int lane = t & 31, warp = t >> 5;
    const int wm = warp >> 2, wn = warp & 3;       // 2 x 4 warp grid
    const int m0 = blockIdx.y * 128, n0 = blockIdx.x * 128;

    // global->smem staging: each thread handles rows (t>>2) and (t>>2)+64,
    // column group (t&3)*4 within the 16-wide k tile.
    const int ldrow = t >> 2;
    const int ldcg  = (t & 3) * 4;
    const float* Ap = A + (size_t)(m0 + ldrow) * K + ldcg;
    const float* Wp = W + (size_t)(n0 + ldrow) * K + ldcg;

    float acc[4][4][4];
#pragma unroll
    for (int i = 0; i < 4; i++)
#pragma unroll
        for (int j = 0; j < 4; j++)
#pragma unroll
            for (int r = 0; r < 4; r++) acc[i][j][r] = 0.f;

    // prologue: stage k-tile 0 into buffer 0
    {
        float4 a0 = *(const float4*)(Ap);
        float4 a1 = *(const float4*)(Ap + (size_t)64 * K);
        float4 b0 = *(const float4*)(Wp);
        float4 b1 = *(const float4*)(Wp + (size_t)64 * K);
        sts_tile(As[0], ldrow,      ldcg, a0);
        sts_tile(As[0], ldrow + 64, ldcg, a1);
        sts_tile(Bs[0], ldrow,      ldcg, b0);
        sts_tile(Bs[0], ldrow + 64, ldcg, b1);
    }
    __syncthreads();

    const int NKT = K / 16;   // 64
    for (int kt = 0; kt < NKT; kt++) {
        const int buf = kt & 1;

        // issue global loads for next tile early
        float4 a0, a1, b0, b1;
        if (kt + 1 < NKT) {
            const float* Ap2 = Ap + (kt + 1) * 16;
            const float* Wp2 = Wp + (kt + 1) * 16;
            a0 = *(const float4*)(Ap2);
            a1 = *(const float4*)(Ap2 + (size_t)64 * K);
            b0 = *(const float4*)(Wp2);
            b1 = *(const float4*)(Wp2 + (size_t)64 * K);
        }

        // compute: two k8 steps from current buffer
#pragma unroll
        for (int s = 0; s < 2; s++) {
            const int g0 = s * 8;
            unsigned af[4][4], bf[4][2];
#pragma unroll
            for (int mf = 0; mf < 4; mf++) {
                int r = wm * 64 + mf * 16 + (lane >> 2);
                const unsigned* p = &As[buf][r * SSTR + g0 + (lane & 3)];
                af[mf][0] = p[0];
                af[mf][1] = p[8 * SSTR];
                af[mf][2] = p[4];
                af[mf][3] = p[8 * SSTR + 4];
            }
#pragma unroll
            for (int nf = 0; nf < 4; nf++) {
                int r = wn * 32 + nf * 8 + (lane >> 2);
                const unsigned* p = &Bs[buf][r * SSTR + g0 + (lane & 3)];
                bf[nf][0] = p[0];
                bf[nf][1] = p[4];
            }
#pragma unroll
            for (int mf = 0; mf < 4; mf++)
#pragma unroll
                for (int nf = 0; nf < 4; nf++) {
                    asm volatile(
                        "mma.sync.aligned.m16n8k8.row.col.f32.tf32.tf32.f32 "
                        "{%0,%1,%2,%3}, {%4,%5,%6,%7}, {%8,%9}, {%0,%1,%2,%3};"
                        : "+f"(acc[mf][nf][0]), "+f"(acc[mf][nf][1]),
                          "+f"(acc[mf][nf][2]), "+f"(acc[mf][nf][3])
                        : "r"(af[mf][0]), "r"(af[mf][1]), "r"(af[mf][2]), "r"(af[mf][3]),
                          "r"(bf[nf][0]), "r"(bf[nf][1]));
                }
        }

        // stage next tile into other buffer
        if (kt + 1 < NKT) {
            const int nb = buf ^ 1;
            sts_tile(As[nb], ldrow,      ldcg, a0);
            sts_tile(As[nb], ldrow + 64, ldcg, a1);
            sts_tile(Bs[nb], ldrow,      ldcg, b0);
            sts_tile(Bs[nb], ldrow + 64, ldcg, b1);
        }
        __syncthreads();
    }

    // epilogue: add bias, write out
#pragma unroll
    for (int nf = 0; nf < 4; nf++) {
        const int col = n0 + wn * 32 + nf * 8 + (lane & 3) * 2;
        const float bv0 = bias[col], bv1 = bias[col + 1];
#pragma unroll
        for (int mf = 0; mf < 4; mf++) {
            const int row = m0 + wm * 64 + mf * 16 + (lane >> 2);
            float2 v0 = make_float2(acc[mf][nf][0] + bv0, acc[mf][nf][1] + bv1);
            float2 v1 = make_float2(acc[mf][nf][2] + bv0, acc[mf][nf][3] + bv1);
            if (MODE == 0) {
                *(float2*)(C + (size_t)row * N + col)       = v0;
                *(float2*)(C + (size_t)(row + 8) * N + col) = v1;
            } else {
                const int h = col >> 6, d = col & 63;
                const int bb0 = row >> 10, t0 = row & 1023;
                *(float2*)(C + ((((size_t)bb0 * H_ + h) * T_ + t0) * DH + d)) = v0;
                const int bb1 = (row + 8) >> 10, t1 = (row + 8) & 1023;
                *(float2*)(C + ((((size_t)bb1 * H_ + h) * T_ + t1) * DH + d)) = v1;
            }
        }
    }
}

// ---------------------------------------------------------------------------
// Fused causal "algebraic" attention (unchanged this round). One pass:
//   w = relu(qk*scale + bias)+1e-6 on kept (k<=q) positions
//   out = (sum_k w*V) / (sum_k w + 1e-6)
// ---------------------------------------------------------------------------
struct AttnSmem {
    float Qst[64][64];   // [d][q]
    float Kst[64][64];   // [d][k]
    float Vs [64][64];   // [k][d]
    float Ws [64][65];   // [q][k]  (padded)
    float bh [64];
    float rs [64];
};

__global__ void __launch_bounds__(256)
attn_kernel(const float* __restrict__ Q, const float* __restrict__ K,
            const float* __restrict__ V, const float* __restrict__ rel_bias,
            float* __restrict__ out)
{
    extern __shared__ char smem_raw[];
    AttnSmem& S = *reinterpret_cast<AttnSmem*>(smem_raw);

    const int qt = blockIdx.x;
    const int h  = blockIdx.y;
    const int b  = blockIdx.z;
    const int tid = threadIdx.x;
    const int tx = tid & 15, ty = tid >> 4;
    const float scale = 0.125f;

    const float* Qg = Q + (((size_t)b * H_ + h) * T_ + qt * 64) * DH;

    if (tid < 2 * MAXREL - 1) S.bh[tid] = rel_bias[tid * H_ + h];

    {
        int q = tid >> 2, d0 = (tid & 3) * 16;
        const float* src = Qg + q * DH + d0;
#pragma unroll
        for (int i = 0; i < 16; i++) S.Qst[d0 + i][q] = src[i];
    }

    float acc[4][4];
    float rsum[4] = {0.f, 0.f, 0.f, 0.f};
#pragma unroll
    for (int i = 0; i < 4; i++)
#pragma unroll
        for (int j = 0; j < 4; j++) acc[i][j] = 0.f;

    __syncthreads();

    const int q0 = qt * 64;
    for (int kt = 0; kt <= qt; kt++) {
        const int k0 = kt * 64;
        const float* Kg = K + (((size_t)b * H_ + h) * T_ + k0) * DH;
        const float* Vg = V + (((size_t)b * H_ + h) * T_ + k0) * DH;
        {
            int k = tid >> 2, d0 = (tid & 3) * 16;
            const float* ks = Kg + k * DH + d0;
#pragma unroll
            for (int i = 0; i < 16; i++) S.Kst[d0 + i][k] = ks[i];
            const float4* vsrc = (const float4*)(Vg + k * DH + d0);
            float4* vdst = (float4*)(&S.Vs[k][d0]);
#pragma unroll
            for (int i = 0; i < 4; i++) vdst[i] = vsrc[i];
        }
        __syncthreads();

        float s[4][4];
#pragma unroll
        for (int i = 0; i < 4; i++)
#pragma unroll
            for (int j = 0; j < 4; j++) s[i][j] = 0.f;
#pragma unroll
        for (int d = 0; d < 64; d++) {
            float4 qv = *(const float4*)&S.Qst[d][ty * 4];
            float4 kv = *(const float4*)&S.Kst[d][tx * 4];
            float qa[4] = {qv.x, qv.y, qv.z, qv.w};
            float ka[4] = {kv.x, kv.y, kv.z, kv.w};
#pragma unroll
            for (int i = 0; i < 4; i++)
#pragma unroll
                for (int j = 0; j < 4; j++)
                    s[i][j] += qa[i] * ka[j];
        }

#pragma unroll
        for (int i = 0; i < 4; i++) {
            int qg = q0 + ty * 4 + i;
#pragma unroll
            for (int j = 0; j < 4; j++) {
                int kg = k0 + tx * 4 + j;
                float w = 0.f;
                if (kg <= qg) {
                    int rel = kg - qg;
                    int u = rel < -(MAXREL - 1) ? 0 : rel + (MAXREL - 1);
                    float v = fmaf(s[i][j], scale, S.bh[u]);
                    w = fmaxf(v, 0.f) + 1e-6f;
                }
                S.Ws[ty * 4 + i][tx * 4 + j] = w;
            }
        }
        __syncthreads();

#pragma unroll
        for (int k = 0; k < 64; k++) {
            float4 vv = *(const float4*)&S.Vs[k][tx * 4];
            float va[4] = {vv.x, vv.y, vv.z, vv.w};
#pragma unroll
            for (int i = 0; i < 4; i++) {
                float w = S.Ws[ty * 4 + i][k];
                if (tx == 0) rsum[i] += w;
#pragma unroll
                for (int j = 0; j < 4; j++)
                    acc[i][j] += w * va[j];
            }
        }
        __syncthreads();
    }

    if (tx == 0) {
#pragma unroll
        for (int i = 0; i < 4; i++) S.rs[ty * 4 + i] = rsum[i];
    }
    __syncthreads();

#pragma unroll
    for (int i = 0; i < 4; i++) {
        int q = q0 + ty * 4 + i;
        float inv = 1.f / (S.rs[ty * 4 + i] + 1e-6f);
        float* dst = out + (((size_t)b * T_ + q) * H_ + h) * DH + tx * 4;
        *(float4*)dst = make_float4(acc[i][0] * inv, acc[i][1] * inv,
                                    acc[i][2] * inv, acc[i][3] * inv);
    }
}

// ---------------------------------------------------------------------------
extern "C" void kernel_launch(void* const* d_in, const int* in_sizes, int n_in,
                              void* d_out, int out_size)
{
    const float* x   = (const float*)d_in[0];
    const float* Wq  = (const float*)d_in[2];
    const float* bq  = (const float*)d_in[3];
    const float* Wk  = (const float*)d_in[4];
    const float* bk  = (const float*)d_in[5];
    const float* Wv  = (const float*)d_in[6];
    const float* bv  = (const float*)d_in[7];
    const float* Wo  = (const float*)d_in[8];
    const float* bo  = (const float*)d_in[9];
    const float* rel = (const float*)d_in[10];

    float *pQ, *pK, *pV, *pA;
    cudaGetSymbolAddress((void**)&pQ, g_Q);
    cudaGetSymbolAddress((void**)&pK, g_K);
    cudaGetSymbolAddress((void**)&pV, g_V);
    cudaGetSymbolAddress((void**)&pA, g_att);

    dim3 gg(C_ / 128, (B_ * T_) / 128);  // (8, 32)
    gemm_tc<1><<<gg, 256>>>(x, Wq, bq, pQ);
    gemm_tc<1><<<gg, 256>>>(x, Wk, bk, pK);
    gemm_tc<1><<<gg, 256>>>(x, Wv, bv, pV);

    int smem = (int)sizeof(AttnSmem);
    cudaFuncSetAttribute(attn_kernel, cudaFuncAttributeMaxDynamicSharedMemorySize, smem);
    attn_kernel<<<dim3(T_ / 64, H_, B_), 256, smem>>>(pQ, pK, pV, rel, pA);

    gemm_tc<0><<<gg, 256>>>(pA, Wo, bo, (float*)d_out);
}

// round 3
// speedup vs baseline: 2.5198x; 1.3737x over previous
#include <cuda_runtime.h>

// Problem constants (fixed by setup_inputs)
#define B_  4
#define T_  1024
#define C_  1024
#define H_  16
#define DH  64
#define MAXREL 32

// Scratch (allocation-free rule: __device__ globals)
__device__ float g_Q[B_*H_*T_*DH];
__device__ float g_K[B_*H_*T_*DH];
__device__ float g_V[B_*H_*T_*DH];
__device__ float g_att[B_*T_*C_];

__device__ __forceinline__ unsigned f2tf32(float x) {
    unsigned r;
    asm("cvt.rna.tf32.f32 %0, %1;" : "=r"(r) : "f"(x));
    return r;
}
__device__ __forceinline__ void split_tf32(float x, unsigned& hi, unsigned& lo) {
    hi = f2tf32(x);
    lo = f2tf32(x - __uint_as_float(hi));
}

#define MMA_TF32(acc, a, b0, b1)                                              \
    asm volatile(                                                             \
        "mma.sync.aligned.m16n8k8.row.col.f32.tf32.tf32.f32 "                 \
        "{%0,%1,%2,%3}, {%4,%5,%6,%7}, {%8,%9}, {%0,%1,%2,%3};"               \
        : "+f"(acc[0]), "+f"(acc[1]), "+f"(acc[2]), "+f"(acc[3])              \
        : "r"(a[0]), "r"(a[1]), "r"(a[2]), "r"(a[3]), "r"(b0), "r"(b1))

// ---------------------------------------------------------------------------
// Tensor-core GEMM: C = A[M,K] @ W[N,K]^T + bias[N], tf32 mma, fp32 accum.
// MODE 0: C row-major [M,N]        MODE 1: C written as [B,H,T,DH]
// ---------------------------------------------------------------------------
#define SSTR 20

__device__ __forceinline__ void sts_tile(unsigned* S, int row, int cg, float4 v) {
    S[row * SSTR + cg + 0] = f2tf32(v.x);
    S[row * SSTR + cg + 1] = f2tf32(v.y);
    S[row * SSTR + cg + 2] = f2tf32(v.z);
    S[row * SSTR + cg + 3] = f2tf32(v.w);
}

template<int MODE>
__global__ void __launch_bounds__(256, 2)
gemm_tc(const float* __restrict__ A, const float* __restrict__ W,
        const float* __restrict__ bias, float* __restrict__ C)
{
    const int K = 1024, N = 1024;
    __shared__ unsigned As[2][128 * SSTR];
    __shared__ unsigned Bs[2][128 * SSTR];

    const int t = threadIdx.x;
    const int lane = t & 31, warp = t >> 5;
    const int wm = warp >> 2, wn = warp & 3;
    const int m0 = blockIdx.y * 128, n0 = blockIdx.x * 128;

    const int ldrow = t >> 2;
    const int ldcg  = (t & 3) * 4;
    const float* Ap = A + (size_t)(m0 + ldrow) * K + ldcg;
    const float* Wp = W + (size_t)(n0 + ldrow) * K + ldcg;

    float acc[4][4][4];
#pragma unroll
    for (int i = 0; i < 4; i++)
#pragma unroll
        for (int j = 0; j < 4; j++)
#pragma unroll
            for (int r = 0; r < 4; r++) acc[i][j][r] = 0.f;

    {
        float4 a0 = *(const float4*)(Ap);
        float4 a1 = *(const float4*)(Ap + (size_t)64 * K);
        float4 b0 = *(const float4*)(Wp);
        float4 b1 = *(const float4*)(Wp + (size_t)64 * K);
        sts_tile(As[0], ldrow,      ldcg, a0);
        sts_tile(As[0], ldrow + 64, ldcg, a1);
        sts_tile(Bs[0], ldrow,      ldcg, b0);
        sts_tile(Bs[0], ldrow + 64, ldcg, b1);
    }
    __syncthreads();

    const int NKT = K / 16;
    for (int kt = 0; kt < NKT; kt++) {
        const int buf = kt & 1;

        float4 a0, a1, b0, b1;
        if (kt + 1 < NKT) {
            const float* Ap2 = Ap + (kt + 1) * 16;
            const float* Wp2 = Wp + (kt + 1) * 16;
            a0 = *(const float4*)(Ap2);
            a1 = *(const float4*)(Ap2 + (size_t)64 * K);
            b0 = *(const float4*)(Wp2);
            b1 = *(const float4*)(Wp2 + (size_t)64 * K);
        }

#pragma unroll
        for (int s = 0; s < 2; s++) {
            const int g0 = s * 8;
            unsigned af[4][4], bf[4][2];
#pragma unroll
            for (int mf = 0; mf < 4; mf++) {
                int r = wm * 64 + mf * 16 + (lane >> 2);
                const unsigned* p = &As[buf][r * SSTR + g0 + (lane & 3)];
                af[mf][0] = p[0];
                af[mf][1] = p[8 * SSTR];
                af[mf][2] = p[4];
                af[mf][3] = p[8 * SSTR + 4];
            }
#pragma unroll
            for (int nf = 0; nf < 4; nf++) {
                int r = wn * 32 + nf * 8 + (lane >> 2);
                const unsigned* p = &Bs[buf][r * SSTR + g0 + (lane & 3)];
                bf[nf][0] = p[0];
                bf[nf][1] = p[4];
            }
#pragma unroll
            for (int mf = 0; mf < 4; mf++)
#pragma unroll
                for (int nf = 0; nf < 4; nf++)
                    MMA_TF32(acc[mf][nf], af[mf], bf[nf][0], bf[nf][1]);
        }

        if (kt + 1 < NKT) {
            const int nb = buf ^ 1;
            sts_tile(As[nb], ldrow,      ldcg, a0);
            sts_tile(As[nb], ldrow + 64, ldcg, a1);
            sts_tile(Bs[nb], ldrow,      ldcg, b0);
            sts_tile(Bs[nb], ldrow + 64, ldcg, b1);
        }
        __syncthreads();
    }

#pragma unroll
    for (int nf = 0; nf < 4; nf++) {
        const int col = n0 + wn * 32 + nf * 8 + (lane & 3) * 2;
        const float bv0 = bias[col], bv1 = bias[col + 1];
#pragma unroll
        for (int mf = 0; mf < 4; mf++) {
            const int row = m0 + wm * 64 + mf * 16 + (lane >> 2);
            float2 v0 = make_float2(acc[mf][nf][0] + bv0, acc[mf][nf][1] + bv1);
            float2 v1 = make_float2(acc[mf][nf][2] + bv0, acc[mf][nf][3] + bv1);
            if (MODE == 0) {
                *(float2*)(C + (size_t)row * N + col)       = v0;
                *(float2*)(C + (size_t)(row + 8) * N + col) = v1;
            } else {
                const int h = col >> 6, d = col & 63;
                const int bb0 = row >> 10, t0 = row & 1023;
                *(float2*)(C + ((((size_t)bb0 * H_ + h) * T_ + t0) * DH + d)) = v0;
                const int bb1 = (row + 8) >> 10, t1 = (row + 8) & 1023;
                *(float2*)(C + ((((size_t)bb1 * H_ + h) * T_ + t1) * DH + d)) = v1;
            }
        }
    }
}

// ---------------------------------------------------------------------------
// Tensor-core fused causal algebraic attention.
//   Stage1 (3xTF32): S = Q @ K^T        (fp32-grade accuracy)
//   epilogue:        w = relu(S*scale + bias[clip]) + 1e-6 (masked -> 0)
//   Stage2 (tf32):   acc += W @ V ;  rsum += row-sums of W (fp32, registers)
//   out = acc / (rsum + 1e-6)
// Block: (b, h, 64 q-rows). 8 warps as 4x2. k-tiles of 64.
// ---------------------------------------------------------------------------
#define AST 68   // smem row stride (words): (4r+c) mod 32 distinct per fragment

__global__ void __launch_bounds__(256, 2)
attn_tc(const float* __restrict__ Q, const float* __restrict__ K,
        const float* __restrict__ V, const float* __restrict__ rel_bias,
        float* __restrict__ out)
{
    extern __shared__ unsigned sm[];
    unsigned* Qhi = sm;
    unsigned* Qlo = Qhi + 64 * AST;
    unsigned* Khi = Qlo + 64 * AST;
    unsigned* Klo = Khi + 64 * AST;
    unsigned* Vt  = Klo + 64 * AST;
    unsigned* Ws  = Vt  + 64 * AST;
    float* bh   = (float*)(Ws + 64 * AST);
    float* rsum = bh + 64;

    const int qt = 15 - (int)blockIdx.x;   // heavy tiles first
    const int h  = blockIdx.y;
    const int b  = blockIdx.z;
    const int t  = threadIdx.x;
    const int lane = t & 31, warp = t >> 5;
    const int wm = warp >> 1, wn = warp & 1;
    const int q0 = qt * 64;

    const float* Qg = Q + (((size_t)b * H_ + h) * T_ + q0) * DH;
    const float* Kb = K + (((size_t)b * H_ + h) * T_) * DH;
    const float* Vb = V + (((size_t)b * H_ + h) * T_) * DH;

    if (t < 2 * MAXREL - 1) bh[t] = rel_bias[t * H_ + h];
    if (t < 64) rsum[t] = 0.f;

    // Load Q tile (hi/lo split)
    {
        const int r = t >> 2, c0 = (t & 3) * 16;
        const float* src = Qg + r * DH + c0;
#pragma unroll
        for (int i = 0; i < 16; i += 4) {
            float4 v = *(const float4*)(src + i);
            float e[4] = {v.x, v.y, v.z, v.w};
#pragma unroll
            for (int j = 0; j < 4; j++) {
                unsigned hi, lo;
                split_tf32(e[j], hi, lo);
                Qhi[r * AST + c0 + i + j] = hi;
                Qlo[r * AST + c0 + i + j] = lo;
            }
        }
    }

    float oacc[4][4];
#pragma unroll
    for (int i = 0; i < 4; i++)
#pragma unroll
        for (int j = 0; j < 4; j++) oacc[i][j] = 0.f;
    float rp0 = 0.f, rp1 = 0.f;

    const int ar  = wm * 16 + (lane >> 2);   // A-fragment base row
    const int nkt = qt + 1;

    for (int kt = 0; kt < nkt; kt++) {
        __syncthreads();   // prev stage2 done reading Vt/Ws before overwrite

        // Load K (hi/lo) and V^T tiles
        {
            const int r = t >> 2, c0 = (t & 3) * 16;
            const float* ks = Kb + (size_t)(kt * 64 + r) * DH + c0;
            const float* vs = Vb + (size_t)(kt * 64 + r) * DH + c0;
#pragma unroll
            for (int i = 0; i < 16; i += 4) {
                float4 kv = *(const float4*)(ks + i);
                float4 vv = *(const float4*)(vs + i);
                float ke[4] = {kv.x, kv.y, kv.z, kv.w};
                float ve[4] = {vv.x, vv.y, vv.z, vv.w};
#pragma unroll
                for (int j = 0; j < 4; j++) {
                    unsigned hi, lo;
                    split_tf32(ke[j], hi, lo);
                    Khi[r * AST + c0 + i + j] = hi;
                    Klo[r * AST + c0 + i + j] = lo;
                    Vt[(c0 + i + j) * AST + r] = f2tf32(ve[j]);
                }
            }
        }
        __syncthreads();

        // Stage 1: S = Q @ K^T with 3xTF32
        float s[4][4];
#pragma unroll
        for (int i = 0; i < 4; i++)
#pragma unroll
            for (int j = 0; j < 4; j++) s[i][j] = 0.f;

#pragma unroll
        for (int ks8 = 0; ks8 < 8; ks8++) {
            const int g0 = ks8 * 8;
            const unsigned* aph = &Qhi[ar * AST + g0 + (lane & 3)];
            const unsigned* apl = &Qlo[ar * AST + g0 + (lane & 3)];
            unsigned ah[4] = {aph[0], aph[8 * AST], aph[4], aph[8 * AST + 4]};
            unsigned al[4] = {apl[0], apl[8 * AST], apl[4], apl[8 * AST + 4]};
#pragma unroll
            for (int nf = 0; nf < 4; nf++) {
                const int br = wn * 32 + nf * 8 + (lane >> 2);
                const unsigned* bph = &Khi[br * AST + g0 + (lane & 3)];
                const unsigned* bpl = &Klo[br * AST + g0 + (lane & 3)];
                unsigned bh0 = bph[0], bh1 = bph[4];
                unsigned bl0 = bpl[0], bl1 = bpl[4];
                MMA_TF32(s[nf], ah, bl0, bl1);   // hi*lo
                MMA_TF32(s[nf], al, bh0, bh1);   // lo*hi
                MMA_TF32(s[nf], ah, bh0, bh1);   // hi*hi
            }
        }

        // Epilogue: bias + causal mask + relu + 1e-6 ; store W (tf32) ; rsum
        {
            const int k0 = kt * 64;
            const int qg0 = q0 + ar;
            const bool diag = (kt == qt);   // only diagonal tile can mask
#pragma unroll
            for (int nf = 0; nf < 4; nf++) {
                const int kg0 = k0 + wn * 32 + nf * 8 + (lane & 3) * 2;
                float w[4];
#pragma unroll
                for (int c = 0; c < 4; c++) {
                    const int qg = qg0 + (c >> 1) * 8;
                    const int kg = kg0 + (c & 1);
                    const int rel = kg - qg;
                    float wv = 0.f;
                    if (!diag || rel <= 0) {
                        const int u = max(rel + (MAXREL - 1), 0);
                        wv = fmaxf(fmaf(s[nf][c], 0.125f, bh[u]), 0.f) + 1e-6f;
                    }
                    w[c] = wv;
                }
                rp0 += w[0] + w[1];
                rp1 += w[2] + w[3];
                const int rl = ar;
                const int cl = wn * 32 + nf * 8 + (lane & 3) * 2;
                *(uint2*)&Ws[rl * AST + cl]       = make_uint2(f2tf32(w[0]), f2tf32(w[1]));
                *(uint2*)&Ws[(rl + 8) * AST + cl] = make_uint2(f2tf32(w[2]), f2tf32(w[3]));
            }
        }
        __syncthreads();

        // Stage 2: oacc += W @ V   (single tf32)
#pragma unroll
        for (int ks8 = 0; ks8 < 8; ks8++) {
            const int g0 = ks8 * 8;
            const unsigned* ap = &Ws[ar * AST + g0 + (lane & 3)];
            unsigned a[4] = {ap[0], ap[8 * AST], ap[4], ap[8 * AST + 4]};
#pragma unroll
            for (int nf = 0; nf < 4; nf++) {
                const int br = wn * 32 + nf * 8 + (lane >> 2);
                const unsigned* bp = &Vt[br * AST + g0 + (lane & 3)];
                MMA_TF32(oacc[nf], a, bp[0], bp[4]);
            }
        }
    }

    // rsum: reduce over the 4 k-column lanes, then across wn warps via atomics
    rp0 += __shfl_xor_sync(0xffffffffu, rp0, 1);
    rp0 += __shfl_xor_sync(0xffffffffu, rp0, 2);
    rp1 += __shfl_xor_sync(0xffffffffu, rp1, 1);
    rp1 += __shfl_xor_sync(0xffffffffu, rp1, 2);
    if ((lane & 3) == 0) {
        atomicAdd(&rsum[ar], rp0);
        atomicAdd(&rsum[ar + 8], rp1);
    }
    __syncthreads();

    const float inv0 = 1.f / (rsum[ar] + 1e-6f);
    const float inv1 = 1.f / (rsum[ar + 8] + 1e-6f);
#pragma unroll
    for (int nf = 0; nf < 4; nf++) {
        const int d = wn * 32 + nf * 8 + (lane & 3) * 2;
        float* dst0 = out + (size_t)(b * T_ + q0 + ar) * C_ + h * DH + d;
        float* dst1 = out + (size_t)(b * T_ + q0 + ar + 8) * C_ + h * DH + d;
        *(float2*)dst0 = make_float2(oacc[nf][0] * inv0, oacc[nf][1] * inv0);
        *(float2*)dst1 = make_float2(oacc[nf][2] * inv1, oacc[nf][3] * inv1);
    }
}

// ---------------------------------------------------------------------------
extern "C" void kernel_launch(void* const* d_in, const int* in_sizes, int n_in,
                              void* d_out, int out_size)
{
    const float* x   = (const float*)d_in[0];
    const float* Wq  = (const float*)d_in[2];
    const float* bq  = (const float*)d_in[3];
    const float* Wk  = (const float*)d_in[4];
    const float* bk  = (const float*)d_in[5];
    const float* Wv  = (const float*)d_in[6];
    const float* bv  = (const float*)d_in[7];
    const float* Wo  = (const float*)d_in[8];
    const float* bo  = (const float*)d_in[9];
    const float* rel = (const float*)d_in[10];

    float *pQ, *pK, *pV, *pA;
    cudaGetSymbolAddress((void**)&pQ, g_Q);
    cudaGetSymbolAddress((void**)&pK, g_K);
    cudaGetSymbolAddress((void**)&pV, g_V);
    cudaGetSymbolAddress((void**)&pA, g_att);

    dim3 gg(C_ / 128, (B_ * T_) / 128);  // (8, 32)
    gemm_tc<1><<<gg, 256>>>(x, Wq, bq, pQ);
    gemm_tc<1><<<gg, 256>>>(x, Wk, bk, pK);
    gemm_tc<1><<<gg, 256>>>(x, Wv, bv, pV);

    const int smem = (6 * 64 * AST + 128) * 4;   // ~105 KB
    static int configured = 0;
    if (!configured) {
        cudaFuncSetAttribute(attn_tc, cudaFuncAttributeMaxDynamicSharedMemorySize, smem);
        configured = 1;
    }
    attn_tc<<<dim3(16, H_, B_), 256, smem>>>(pQ, pK, pV, rel, pA);

    gemm_tc<0><<<gg, 256>>>(pA, Wo, bo, (float*)d_out);
}

// round 5
// speedup vs baseline: 3.0393x; 1.2062x over previous
#include <cuda_runtime.h>
#include <cuda_bf16.h>
#include <cstdint>

// Problem constants (fixed by setup_inputs)
#define B_  4
#define T_  1024
#define C_  1024
#define H_  16
#define DH  64
#define MAXREL 32

// Scratch (allocation-free rule: __device__ globals)
__device__ unsigned g_Qhi[B_*H_*T_*DH/2], g_Qlo[B_*H_*T_*DH/2];  // bf16x2 packed pairs
__device__ unsigned g_Khi[B_*H_*T_*DH/2], g_Klo[B_*H_*T_*DH/2];
__device__ unsigned g_Vt [B_*H_*DH*T_];                          // tf32, [B,H,D,T]
__device__ float    g_att[B_*T_*C_];

__device__ __forceinline__ unsigned f2tf32(float x) {
    unsigned r;
    asm("cvt.rna.tf32.f32 %0, %1;" : "=r"(r) : "f"(x));
    return r;
}
__device__ __forceinline__ uint32_t smem_u32(const void* p) {
    uint32_t a;
    asm("{ .reg .u64 t; cvta.to.shared.u64 t, %1; cvt.u32.u64 %0, t; }"
        : "=r"(a) : "l"(p));
    return a;
}

#define MMA_TF32(acc, a, b0, b1)                                              \
    asm volatile(                                                             \
        "mma.sync.aligned.m16n8k8.row.col.f32.tf32.tf32.f32 "                 \
        "{%0,%1,%2,%3}, {%4,%5,%6,%7}, {%8,%9}, {%0,%1,%2,%3};"               \
        : "+f"(acc[0]), "+f"(acc[1]), "+f"(acc[2]), "+f"(acc[3])              \
        : "r"(a[0]), "r"(a[1]), "r"(a[2]), "r"(a[3]), "r"(b0), "r"(b1))

#define MMA_BF16(acc, a, b0, b1)                                              \
    asm volatile(                                                             \
        "mma.sync.aligned.m16n8k16.row.col.f32.bf16.bf16.f32 "                \
        "{%0,%1,%2,%3}, {%4,%5,%6,%7}, {%8,%9}, {%0,%1,%2,%3};"               \
        : "+f"(acc[0]), "+f"(acc[1]), "+f"(acc[2]), "+f"(acc[3])              \
        : "r"(a[0]), "r"(a[1]), "r"(a[2]), "r"(a[3]), "r"(b0), "r"(b1))

#define CP_ASYNC16(saddr, gptr)                                               \
    asm volatile("cp.async.cg.shared.global [%0], [%1], 16;"                  \
                 :: "r"(saddr), "l"(gptr) : "memory")
#define CP_COMMIT()      asm volatile("cp.async.commit_group;" ::: "memory")
#define CP_WAIT(n)       asm volatile("cp.async.wait_group %0;" :: "n"(n) : "memory")

// ---------------------------------------------------------------------------
// Tensor-core GEMM: C = A[M,K] @ W[N,K]^T + bias[N], tf32 mma, fp32 accum.
// MODE 0: C row-major [M,N]
// MODE 2: outputs packed bf16 hi/lo pairs, layout [B,H,T,DH/2]  (Q, K)
// MODE 3: outputs tf32 u32, transposed layout [B,H,DH,T]        (V)
// ---------------------------------------------------------------------------
#define SSTR 20

__device__ __forceinline__ void sts_tile(unsigned* S, int row, int cg, float4 v) {
    S[row * SSTR + cg + 0] = f2tf32(v.x);
    S[row * SSTR + cg + 1] = f2tf32(v.y);
    S[row * SSTR + cg + 2] = f2tf32(v.z);
    S[row * SSTR + cg + 3] = f2tf32(v.w);
}

__device__ __forceinline__ void store_hilo(unsigned* Phi, unsigned* Plo, size_t off,
                                           float x, float y) {
    __nv_bfloat16 hx = __float2bfloat16(x), hy = __float2bfloat16(y);
    __nv_bfloat162 h2(hx, hy);
    __nv_bfloat162 l2(__float2bfloat16(x - __bfloat162float(hx)),
                      __float2bfloat16(y - __bfloat162float(hy)));
    Phi[off] = *(unsigned*)&h2;
    Plo[off] = *(unsigned*)&l2;
}

template<int MODE>
__global__ void __launch_bounds__(256, 2)
gemm_tc(const float* __restrict__ A, const float* __restrict__ W,
        const float* __restrict__ bias, float* __restrict__ C,
        unsigned* __restrict__ Phi, unsigned* __restrict__ Plo)
{
    const int K = 1024, N = 1024;
    __shared__ unsigned As[2][128 * SSTR];
    __shared__ unsigned Bs[2][128 * SSTR];

    const int t = threadIdx.x;
    const int lane = t & 31, warp = t >> 5;
    const int wm = warp >> 2, wn = warp & 3;
    const int m0 = blockIdx.y * 128, n0 = blockIdx.x * 128;

    const int ldrow = t >> 2;
    const int ldcg  = (t & 3) * 4;
    const float* Ap = A + (size_t)(m0 + ldrow) * K + ldcg;
    const float* Wp = W + (size_t)(n0 + ldrow) * K + ldcg;

    float acc[4][4][4];
#pragma unroll
    for (int i = 0; i < 4; i++)
#pragma unroll
        for (int j = 0; j < 4; j++)
#pragma unroll
            for (int r = 0; r < 4; r++) acc[i][j][r] = 0.f;

    {
        float4 a0 = *(const float4*)(Ap);
        float4 a1 = *(const float4*)(Ap + (size_t)64 * K);
        float4 b0 = *(const float4*)(Wp);
        float4 b1 = *(const float4*)(Wp + (size_t)64 * K);
        sts_tile(As[0], ldrow,      ldcg, a0);
        sts_tile(As[0], ldrow + 64, ldcg, a1);
        sts_tile(Bs[0], ldrow,      ldcg, b0);
        sts_tile(Bs[0], ldrow + 64, ldcg, b1);
    }
    __syncthreads();

    const int NKT = K / 16;
    for (int kt = 0; kt < NKT; kt++) {
        const int buf = kt & 1;

        float4 a0, a1, b0, b1;
        if (kt + 1 < NKT) {
            const float* Ap2 = Ap + (kt + 1) * 16;
            const float* Wp2 = Wp + (kt + 1) * 16;
            a0 = *(const float4*)(Ap2);
            a1 = *(const float4*)(Ap2 + (size_t)64 * K);
            b0 = *(const float4*)(Wp2);
            b1 = *(const float4*)(Wp2 + (size_t)64 * K);
        }

#pragma unroll
        for (int s = 0; s < 2; s++) {
            const int g0 = s * 8;
            unsigned af[4][4], bf[4][2];
#pragma unroll
            for (int mf = 0; mf < 4; mf++) {
                int r = wm * 64 + mf * 16 + (lane >> 2);
                const unsigned* p = &As[buf][r * SSTR + g0 + (lane & 3)];
                af[mf][0] = p[0];
                af[mf][1] = p[8 * SSTR];
                af[mf][2] = p[4];
                af[mf][3] = p[8 * SSTR + 4];
            }
#pragma unroll
            for (int nf = 0; nf < 4; nf++) {
                int r = wn * 32 + nf * 8 + (lane >> 2);
                const unsigned* p = &Bs[buf][r * SSTR + g0 + (lane & 3)];
                bf[nf][0] = p[0];
                bf[nf][1] = p[4];
            }
#pragma unroll
            for (int mf = 0; mf < 4; mf++)
#pragma unroll
                for (int nf = 0; nf < 4; nf++)
                    MMA_TF32(acc[mf][nf], af[mf], bf[nf][0], bf[nf][1]);
        }

        if (kt + 1 < NKT) {
            const int nb = buf ^ 1;
            sts_tile(As[nb], ldrow,      ldcg, a0);
            sts_tile(As[nb], ldrow + 64, ldcg, a1);
            sts_tile(Bs[nb], ldrow,      ldcg, b0);
            sts_tile(Bs[nb], ldrow + 64, ldcg, b1);
        }
        __syncthreads();
    }

#pragma unroll
    for (int nf = 0; nf < 4; nf++) {
        const int col = n0 + wn * 32 + nf * 8 + (lane & 3) * 2;
        const float bv0 = bias[col], bv1 = bias[col + 1];
#pragma unroll
        for (int mf = 0; mf < 4; mf++) {
            const int row = m0 + wm * 64 + mf * 16 + (lane >> 2);
            float2 v0 = make_float2(acc[mf][nf][0] + bv0, acc[mf][nf][1] + bv1);
            float2 v1 = make_float2(acc[mf][nf][2] + bv0, acc[mf][nf][3] + bv1);
            if (MODE == 0) {
                *(float2*)(C + (size_t)row * N + col)       = v0;
                *(float2*)(C + (size_t)(row + 8) * N + col) = v1;
            } else if (MODE == 2) {
                const int h = col >> 6, d = col & 63, pr = d >> 1;
                const int bb = row >> 10, tt = row & 1023;
                const size_t off = ((((size_t)bb * H_ + h) * T_ + tt) * 32) + pr;
                store_hilo(Phi, Plo, off,            v0.x, v0.y);
                store_hilo(Phi, Plo, off + 8 * 32,   v1.x, v1.y);
            } else {  // MODE 3: V transposed tf32 [B,H,D,T]
                const int h = col >> 6, d = col & 63;
                const int bb = row >> 10, tt = row & 1023;
                const size_t vb = (((size_t)bb * H_ + h) * DH + d) * T_ + tt;
                Phi[vb]           = f2tf32(v0.x);
                Phi[vb + T_]      = f2tf32(v0.y);
                Phi[vb + 8]       = f2tf32(v1.x);
                Phi[vb + T_ + 8]  = f2tf32(v1.y);
            }
        }
    }
}

// ---------------------------------------------------------------------------
// Fused causal algebraic attention, v2.
//   Stage1: S = Q @ K^T via bf16 hi/lo 3-term mma (m16n8k16), fp32 accum.
//   epilogue: w = relu(S*scale + bias[clip]) + 1e-6 (masked -> 0) -> Ws (tf32)
//   Stage2: oacc += W @ V via tf32 mma (m16n8k8); rsum in registers.
//   out = oacc / (rsum + 1e-6)
// Q/K pre-split bf16 hi/lo packed pairs; V pre-transposed tf32 [B,H,D,T].
// Loads via cp.async; V-tile load overlaps stage1. 72KB smem -> 3 CTA/SM.
// ---------------------------------------------------------------------------
#define PST 36   // stride (u32) for packed bf16 tiles: 36r+c mod 32 = 4r+c distinct
#define AST 68   // stride (u32) for tf32 tiles

__global__ void __launch_bounds__(256, 3)
attn_v2(const unsigned* __restrict__ Qhi, const unsigned* __restrict__ Qlo,
        const unsigned* __restrict__ Khi, const unsigned* __restrict__ Klo,
        const unsigned* __restrict__ Vtg, const float* __restrict__ rel_bias,
        float* __restrict__ out)
{
    extern __shared__ unsigned sm[];
    unsigned* Qh_s = sm;               // 64*36
    unsigned* Ql_s = Qh_s + 64 * PST;
    unsigned* Kh_s = Ql_s + 64 * PST;
    unsigned* Kl_s = Kh_s + 64 * PST;
    unsigned* Vt_s = Kl_s + 64 * PST;  // 64*68
    unsigned* Ws_s = Vt_s + 64 * AST;  // 64*68
    float* bh   = (float*)(Ws_s + 64 * AST);
    float* rsum = bh + 64;

    const int qt = 15 - (int)blockIdx.x;   // heavy tiles first
    const int h  = blockIdx.y;
    const int b  = blockIdx.z;
    const int t  = threadIdx.x;
    const int lane = t & 31, warp = t >> 5;
    const int wm = warp >> 1, wn = warp & 1;
    const int q0 = qt * 64;
    const int bhx = b * H_ + h;

    const int r4  = t >> 2;
    const int cp8 = (t & 3) * 8;    // u32 col for packed K/Q rows (32 wide)
    const int cv16 = (t & 3) * 16;  // u32 col for Vt rows (64 wide)

    // prologue: Q tile via cp.async (group 0)
    {
        const size_t qoff = ((size_t)bhx * T_ + q0 + r4) * 32 + cp8;
        CP_ASYNC16(smem_u32(&Qh_s[r4 * PST + cp8]),     Qhi + qoff);
        CP_ASYNC16(smem_u32(&Qh_s[r4 * PST + cp8 + 4]), Qhi + qoff + 4);
        CP_ASYNC16(smem_u32(&Ql_s[r4 * PST + cp8]),     Qlo + qoff);
        CP_ASYNC16(smem_u32(&Ql_s[r4 * PST + cp8 + 4]), Qlo + qoff + 4);
        CP_COMMIT();
    }
    if (t < 2 * MAXREL - 1) bh[t] = rel_bias[t * H_ + h];
    if (t < 64) rsum[t] = 0.f;

    const unsigned* Khg = Khi + (size_t)bhx * T_ * 32;
    const unsigned* Klg = Klo + (size_t)bhx * T_ * 32;
    const unsigned* Vbg = Vtg + (size_t)bhx * DH * T_;

    float oacc[4][4];
#pragma unroll
    for (int i = 0; i < 4; i++)
#pragma unroll
        for (int j = 0; j < 4; j++) oacc[i][j] = 0.f;
    float rp0 = 0.f, rp1 = 0.f;

    const int ar = wm * 16 + (lane >> 2);

    for (int kt = 0; kt <= qt; kt++) {
        const int k0 = kt * 64;
        __syncthreads();   // prev stage1/2 done with Kh/Kl/Vt/Ws

        // K hi/lo tile (group), then V tile (group)
        {
            const size_t koff = (size_t)(k0 + r4) * 32 + cp8;
            CP_ASYNC16(smem_u32(&Kh_s[r4 * PST + cp8]),     Khg + koff);
            CP_ASYNC16(smem_u32(&Kh_s[r4 * PST + cp8 + 4]), Khg + koff + 4);
            CP_ASYNC16(smem_u32(&Kl_s[r4 * PST + cp8]),     Klg + koff);
            CP_ASYNC16(smem_u32(&Kl_s[r4 * PST + cp8 + 4]), Klg + koff + 4);
            CP_COMMIT();
            const size_t voff = (size_t)r4 * T_ + k0 + cv16;
            CP_ASYNC16(smem_u32(&Vt_s[r4 * AST + cv16]),      Vbg + voff);
            CP_ASYNC16(smem_u32(&Vt_s[r4 * AST + cv16 + 4]),  Vbg + voff + 4);
            CP_ASYNC16(smem_u32(&Vt_s[r4 * AST + cv16 + 8]),  Vbg + voff + 8);
            CP_ASYNC16(smem_u32(&Vt_s[r4 * AST + cv16 + 12]), Vbg + voff + 12);
            CP_COMMIT();
        }
        CP_WAIT(1);        // Q (first iter) + K done; V may still fly
        __syncthreads();

        // Stage 1: S = Q @ K^T, bf16 3-term (hi*hi + hi*lo + lo*hi)
        float s[4][4];
#pragma unroll
        for (int i = 0; i < 4; i++)
#pragma unroll
            for (int j = 0; j < 4; j++) s[i][j] = 0.f;

#pragma unroll
        for (int st = 0; st < 4; st++) {
            const int g0 = st * 8;
            const unsigned* ahp = &Qh_s[ar * PST + g0 + (lane & 3)];
            const unsigned* alp = &Ql_s[ar * PST + g0 + (lane & 3)];
            unsigned ah[4] = {ahp[0], ahp[8 * PST], ahp[4], ahp[8 * PST + 4]};
            unsigned al[4] = {alp[0], alp[8 * PST], alp[4], alp[8 * PST + 4]};
#pragma unroll
            for (int nf = 0; nf < 4; nf++) {
                const int br = wn * 32 + nf * 8 + (lane >> 2);
                const unsigned* bhp = &Kh_s[br * PST + g0 + (lane & 3)];
                const unsigned* blp = &Kl_s[br * PST + g0 + (lane & 3)];
                unsigned b0 = bhp[0], b1 = bhp[4];
                unsigned c0 = blp[0], c1 = blp[4];
                MMA_BF16(s[nf], ah, b0, b1);
                MMA_BF16(s[nf], ah, c0, c1);
                MMA_BF16(s[nf], al, b0, b1);
            }
        }

        // Epilogue: scale + clipped rel bias + causal mask + relu + 1e-6
        {
            const int qg0 = q0 + ar;
            const bool diag = (kt == qt);
#pragma unroll
            for (int nf = 0; nf < 4; nf++) {
                const int kg0 = k0 + wn * 32 + nf * 8 + (lane & 3) * 2;
                float w[4];
#pragma unroll
                for (int c = 0; c < 4; c++) {
                    const int qg = qg0 + (c >> 1) * 8;
                    const int kg = kg0 + (c & 1);
                    const int rel = kg - qg;
                    float wv = 0.f;
                    if (!diag || rel <= 0) {
                        const int u = max(rel + (MAXREL - 1), 0);
                        wv = fmaxf(fmaf(s[nf][c], 0.125f, bh[u]), 0.f) + 1e-6f;
                    }
                    w[c] = wv;
                }
                rp0 += w[0] + w[1];
                rp1 += w[2] + w[3];
                const int cl = wn * 32 + nf * 8 + (lane & 3) * 2;
                *(uint2*)&Ws_s[ar * AST + cl]       = make_uint2(f2tf32(w[0]), f2tf32(w[1]));
                *(uint2*)&Ws_s[(ar + 8) * AST + cl] = make_uint2(f2tf32(w[2]), f2tf32(w[3]));
            }
        }
        CP_WAIT(0);        // V tile arrived
        __syncthreads();   // Ws visible + Vt visible

        // Stage 2: oacc += W @ V (tf32)
#pragma unroll
        for (int ks8 = 0; ks8 < 8; ks8++) {
            const int g0 = ks8 * 8;
            const unsigned* ap = &Ws_s[ar * AST + g0 + (lane & 3)];
            unsigned a[4] = {ap[0], ap[8 * AST], ap[4], ap[8 * AST + 4]};
#pragma unroll
            for (int nf = 0; nf < 4; nf++) {
                const int br = wn * 32 + nf * 8 + (lane >> 2);
                const unsigned* bp = &Vt_s[br * AST + g0 + (lane & 3)];
                MMA_TF32(oacc[nf], a, bp[0], bp[4]);
            }
        }
    }

    // rsum: reduce over 4 k-lanes, then across the 2 wn warps via smem atomics
    rp0 += __shfl_xor_sync(0xffffffffu, rp0, 1);
    rp0 += __shfl_xor_sync(0xffffffffu, rp0, 2);
    rp1 += __shfl_xor_sync(0xffffffffu, rp1, 1);
    rp1 += __shfl_xor_sync(0xffffffffu, rp1, 2);
    if ((lane & 3) == 0) {
        atomicAdd(&rsum[ar], rp0);
        atomicAdd(&rsum[ar + 8], rp1);
    }
    __syncthreads();

    const float inv0 = 1.f / (rsum[ar] + 1e-6f);
    const float inv1 = 1.f / (rsum[ar + 8] + 1e-6f);
#pragma unroll
    for (int nf = 0; nf < 4; nf++) {
        const int d = wn * 32 + nf * 8 + (lane & 3) * 2;
        float* dst0 = out + (size_t)(b * T_ + q0 + ar) * C_ + h * DH + d;
        float* dst1 = out + (size_t)(b * T_ + q0 + ar + 8) * C_ + h * DH + d;
        *(float2*)dst0 = make_float2(oacc[nf][0] * inv0, oacc[nf][1] * inv0);
        *(float2*)dst1 = make_float2(oacc[nf][2] * inv1, oacc[nf][3] * inv1);
    }
}

#define ATTN_SMEM ((4 * 64 * PST + 2 * 64 * AST + 128) * 4)   // 72192 B

// ---------------------------------------------------------------------------
extern "C" void kernel_launch(void* const* d_in, const int* in_sizes, int n_in,
                              void* d_out, int out_size)
{
    const float* x   = (const float*)d_in[0];
    const float* Wq  = (const float*)d_in[2];
    const float* bq  = (const float*)d_in[3];
    const float* Wk  = (const float*)d_in[4];
    const float* bk  = (const float*)d_in[5];
    const float* Wv  = (const float*)d_in[6];
    const float* bv  = (const float*)d_in[7];
    const float* Wo  = (const float*)d_in[8];
    const float* bo  = (const float*)d_in[9];
    const float* rel = (const float*)d_in[10];

    unsigned *qhi, *qlo, *khi, *klo, *vt;
    float* pA;
    cudaGetSymbolAddress((void**)&qhi, g_Qhi);
    cudaGetSymbolAddress((void**)&qlo, g_Qlo);
    cudaGetSymbolAddress((void**)&khi, g_Khi);
    cudaGetSymbolAddress((void**)&klo, g_Klo);
    cudaGetSymbolAddress((void**)&vt,  g_Vt);
    cudaGetSymbolAddress((void**)&pA,  g_att);

    static int configured = 0;
    if (!configured) {
        cudaFuncSetAttribute(attn_v2, cudaFuncAttributeMaxDynamicSharedMemorySize,
                             ATTN_SMEM);
        configured = 1;
    }

    dim3 gg(C_ / 128, (B_ * T_) / 128);  // (8, 32)
    gemm_tc<2><<<gg, 256>>>(x, Wq, bq, nullptr, qhi, qlo);
    gemm_tc<2><<<gg, 256>>>(x, Wk, bk, nullptr, khi, klo);
    gemm_tc<3><<<gg, 256>>>(x, Wv, bv, nullptr, vt, nullptr);

    attn_v2<<<dim3(16, H_, B_), 256, ATTN_SMEM>>>(qhi, qlo, khi, klo, vt, rel, pA);

    gemm_tc<0><<<gg, 256>>>(pA, Wo, bo, (float*)d_out, nullptr, nullptr);
}

// round 7
// speedup vs baseline: 3.3652x; 1.1072x over previous
#include <cuda_runtime.h>
#include <cuda_bf16.h>
#include <cuda_fp16.h>
#include <cstdint>

// Problem constants (fixed by setup_inputs)
#define B_  4
#define T_  1024
#define C_  1024
#define H_  16
#define DH  64
#define MAXREL 32

// Scratch (allocation-free rule: __device__ globals)
__device__ unsigned g_Qhi[B_*H_*T_*DH/2], g_Qlo[B_*H_*T_*DH/2];  // bf16x2 packed pairs
__device__ unsigned g_Khi[B_*H_*T_*DH/2], g_Klo[B_*H_*T_*DH/2];
__device__ unsigned g_Vt [B_*H_*DH*T_];                          // tf32, [B,H,D,T]
__device__ float    g_att[B_*T_*C_];

__device__ __forceinline__ unsigned f2tf32(float x) {
    unsigned r;
    asm("cvt.rna.tf32.f32 %0, %1;" : "=r"(r) : "f"(x));
    return r;
}
__device__ __forceinline__ unsigned pack_half2(float x, float y) {
    __half2 h = __floats2half2_rn(x, y);
    return *(unsigned*)&h;
}
__device__ __forceinline__ uint32_t smem_u32(const void* p) {
    uint32_t a;
    asm("{ .reg .u64 t; cvta.to.shared.u64 t, %1; cvt.u32.u64 %0, t; }"
        : "=r"(a) : "l"(p));
    return a;
}

#define MMA_TF32(acc, a, b0, b1)                                              \
    asm volatile(                                                             \
        "mma.sync.aligned.m16n8k8.row.col.f32.tf32.tf32.f32 "                 \
        "{%0,%1,%2,%3}, {%4,%5,%6,%7}, {%8,%9}, {%0,%1,%2,%3};"               \
        : "+f"(acc[0]), "+f"(acc[1]), "+f"(acc[2]), "+f"(acc[3])              \
        : "r"(a[0]), "r"(a[1]), "r"(a[2]), "r"(a[3]), "r"(b0), "r"(b1))

#define MMA_BF16(acc, a, b0, b1)                                              \
    asm volatile(                                                             \
        "mma.sync.aligned.m16n8k16.row.col.f32.bf16.bf16.f32 "                \
        "{%0,%1,%2,%3}, {%4,%5,%6,%7}, {%8,%9}, {%0,%1,%2,%3};"               \
        : "+f"(acc[0]), "+f"(acc[1]), "+f"(acc[2]), "+f"(acc[3])              \
        : "r"(a[0]), "r"(a[1]), "r"(a[2]), "r"(a[3]), "r"(b0), "r"(b1))

#define MMA_FP16(acc, a, b0, b1)                                              \
    asm volatile(                                                             \
        "mma.sync.aligned.m16n8k16.row.col.f32.f16.f16.f32 "                  \
        "{%0,%1,%2,%3}, {%4,%5,%6,%7}, {%8,%9}, {%0,%1,%2,%3};"               \
        : "+f"(acc[0]), "+f"(acc[1]), "+f"(acc[2]), "+f"(acc[3])              \
        : "r"(a[0]), "r"(a[1]), "r"(a[2]), "r"(a[3]), "r"(b0), "r"(b1))

#define CP_ASYNC16(saddr, gptr)                                               \
    asm volatile("cp.async.cg.shared.global [%0], [%1], 16;"                  \
                 :: "r"(saddr), "l"(gptr) : "memory")
#define CP_COMMIT()      asm volatile("cp.async.commit_group;" ::: "memory")
#define CP_WAIT(n)       asm volatile("cp.async.wait_group %0;" :: "n"(n) : "memory")

// ---------------------------------------------------------------------------
// fp16 tensor-core GEMM: C = A[M,K] @ W[N,K]^T + bias[N], f32 accum.
// m16n8k16: 2x MACs/instruction vs tf32 k8, same 11-bit significand class.
// Tiles 128x128xBK16, 256 threads (8 warps 2x4), warp tile 64x32.
// smem: packed half2, 8 u32/row/chunk, row stride 12 (conflict-free frags).
// MODE 0: C row-major [M,N]
// MODE 2: packed bf16 hi/lo pairs out, layout [B,H,T,DH/2]  (Q, K)
// MODE 3: tf32 u32 out, transposed layout [B,H,DH,T]        (V)
// ---------------------------------------------------------------------------
#define HST 12

__device__ __forceinline__ void sts_half(unsigned* S, int row, int cg,
                                         float4 v0, float4 v1) {
    uint4 u;
    u.x = pack_half2(v0.x, v0.y);
    u.y = pack_half2(v0.z, v0.w);
    u.z = pack_half2(v1.x, v1.y);
    u.w = pack_half2(v1.z, v1.w);
    *(uint4*)&S[row * HST + cg] = u;
}

__device__ __forceinline__ void store_hilo(unsigned* Phi, unsigned* Plo, size_t off,
                                           float x, float y) {
    __nv_bfloat16 hx = __float2bfloat16(x), hy = __float2bfloat16(y);
    __nv_bfloat162 h2(hx, hy);
    __nv_bfloat162 l2(__float2bfloat16(x - __bfloat162float(hx)),
                      __float2bfloat16(y - __bfloat162float(hy)));
    Phi[off] = *(unsigned*)&h2;
    Plo[off] = *(unsigned*)&l2;
}

template<int MODE>
__global__ void __launch_bounds__(256, 2)
gemm_hc(const float* __restrict__ A, const float* __restrict__ W,
        const float* __restrict__ bias, float* __restrict__ C,
        unsigned* __restrict__ Phi, unsigned* __restrict__ Plo)
{
    const int K = 1024, N = 1024;
    __shared__ unsigned As[2][128 * HST];
    __shared__ unsigned Bs[2][128 * HST];

    const int t = threadIdx.x;
    const int lane = t & 31, warp = t >> 5;
    const int wm = warp >> 2, wn = warp & 3;
    const int m0 = blockIdx.y * 128, n0 = blockIdx.x * 128;

    // staging: thread covers row (t>>1), float cols [seg*8, seg*8+8)
    const int ldrow = t >> 1;
    const int seg   = t & 1;
    const float* Ap = A + (size_t)(m0 + ldrow) * K + seg * 8;
    const float* Wp = W + (size_t)(n0 + ldrow) * K + seg * 8;

    float acc[4][4][4];
#pragma unroll
    for (int i = 0; i < 4; i++)
#pragma unroll
        for (int j = 0; j < 4; j++)
#pragma unroll
            for (int r = 0; r < 4; r++) acc[i][j][r] = 0.f;

    // prologue: stage k-tile 0
    {
        float4 a0 = *(const float4*)(Ap);
        float4 a1 = *(const float4*)(Ap + 4);
        float4 b0 = *(const float4*)(Wp);
        float4 b1 = *(const float4*)(Wp + 4);
        sts_half(As[0], ldrow, seg * 4, a0, a1);
        sts_half(Bs[0], ldrow, seg * 4, b0, b1);
    }
    __syncthreads();

    const int NKT = K / 16;   // 64
    for (int kt = 0; kt < NKT; kt++) {
        const int buf = kt & 1;

        float4 a0, a1, b0, b1;
        if (kt + 1 < NKT) {
            const float* Ap2 = Ap + (kt + 1) * 16;
            const float* Wp2 = Wp + (kt + 1) * 16;
            a0 = *(const float4*)(Ap2);
            a1 = *(const float4*)(Ap2 + 4);
            b0 = *(const float4*)(Wp2);
            b1 = *(const float4*)(Wp2 + 4);
        }

        // 16 MMAs covering 128x128 x k16
        unsigned af[4][4], bf[4][2];
#pragma unroll
        for (int mf = 0; mf < 4; mf++) {
            const int r = wm * 64 + mf * 16 + (lane >> 2);
            const unsigned* p = &As[buf][r * HST + (lane & 3)];
            af[mf][0] = p[0];
            af[mf][1] = p[8 * HST];
            af[mf][2] = p[4];
            af[mf][3] = p[8 * HST + 4];
        }
#pragma unroll
        for (int nf = 0; nf < 4; nf++) {
            const int r = wn * 32 + nf * 8 + (lane >> 2);
            const unsigned* p = &Bs[buf][r * HST + (lane & 3)];
            bf[nf][0] = p[0];
            bf[nf][1] = p[4];
        }
#pragma unroll
        for (int mf = 0; mf < 4; mf++)
#pragma unroll
            for (int nf = 0; nf < 4; nf++)
                MMA_FP16(acc[mf][nf], af[mf], bf[nf][0], bf[nf][1]);

        if (kt + 1 < NKT) {
            const int nb = buf ^ 1;
            sts_half(As[nb], ldrow, seg * 4, a0, a1);
            sts_half(Bs[nb], ldrow, seg * 4, b0, b1);
        }
        __syncthreads();
    }

    // epilogue
#pragma unroll
    for (int nf = 0; nf < 4; nf++) {
        const int col = n0 + wn * 32 + nf * 8 + (lane & 3) * 2;
        const float bv0 = bias[col], bv1 = bias[col + 1];
#pragma unroll
        for (int mf = 0; mf < 4; mf++) {
            const int row = m0 + wm * 64 + mf * 16 + (lane >> 2);
            float2 v0 = make_float2(acc[mf][nf][0] + bv0, acc[mf][nf][1] + bv1);
            float2 v1 = make_float2(acc[mf][nf][2] + bv0, acc[mf][nf][3] + bv1);
            if (MODE == 0) {
                *(float2*)(C + (size_t)row * N + col)       = v0;
                *(float2*)(C + (size_t)(row + 8) * N + col) = v1;
            } else if (MODE == 2) {
                const int h = col >> 6, d = col & 63, pr = d >> 1;
                const int bb = row >> 10, tt = row & 1023;
                const size_t off = ((((size_t)bb * H_ + h) * T_ + tt) * 32) + pr;
                store_hilo(Phi, Plo, off,          v0.x, v0.y);
                store_hilo(Phi, Plo, off + 8 * 32, v1.x, v1.y);
            } else {  // MODE 3: V transposed tf32 [B,H,D,T]
                const int h = col >> 6, d = col & 63;
                const int bb = row >> 10, tt = row & 1023;
                const size_t vb = (((size_t)bb * H_ + h) * DH + d) * T_ + tt;
                Phi[vb]          = f2tf32(v0.x);
                Phi[vb + T_]     = f2tf32(v0.y);
                Phi[vb + 8]      = f2tf32(v1.x);
                Phi[vb + T_ + 8] = f2tf32(v1.y);
            }
        }
    }
}

// ---------------------------------------------------------------------------
// Fused causal algebraic attention (unchanged from round 5).
// ---------------------------------------------------------------------------
#define PST 36
#define AST 68

__global__ void __launch_bounds__(256, 3)
attn_v2(const unsigned* __restrict__ Qhi, const unsigned* __restrict__ Qlo,
        const unsigned* __restrict__ Khi, const unsigned* __restrict__ Klo,
        const unsigned* __restrict__ Vtg, const float* __restrict__ rel_bias,
        float* __restrict__ out)
{
    extern __shared__ unsigned sm[];
    unsigned* Qh_s = sm;
    unsigned* Ql_s = Qh_s + 64 * PST;
    unsigned* Kh_s = Ql_s + 64 * PST;
    unsigned* Kl_s = Kh_s + 64 * PST;
    unsigned* Vt_s = Kl_s + 64 * PST;
    unsigned* Ws_s = Vt_s + 64 * AST;
    float* bh   = (float*)(Ws_s + 64 * AST);
    float* rsum = bh + 64;

    const int qt = 15 - (int)blockIdx.x;
    const int h  = blockIdx.y;
    const int b  = blockIdx.z;
    const int t  = threadIdx.x;
    const int lane = t & 31, warp = t >> 5;
    const int wm = warp >> 1, wn = warp & 1;
    const int q0 = qt * 64;
    const int bhx = b * H_ + h;

    const int r4   = t >> 2;
    const int cp8  = (t & 3) * 8;
    const int cv16 = (t & 3) * 16;

    {
        const size_t qoff = ((size_t)bhx * T_ + q0 + r4) * 32 + cp8;
        CP_ASYNC16(smem_u32(&Qh_s[r4 * PST + cp8]),     Qhi + qoff);
        CP_ASYNC16(smem_u32(&Qh_s[r4 * PST + cp8 + 4]), Qhi + qoff + 4);
        CP_ASYNC16(smem_u32(&Ql_s[r4 * PST + cp8]),     Qlo + qoff);
        CP_ASYNC16(smem_u32(&Ql_s[r4 * PST + cp8 + 4]), Qlo + qoff + 4);
        CP_COMMIT();
    }
    if (t < 2 * MAXREL - 1) bh[t] = rel_bias[t * H_ + h];
    if (t < 64) rsum[t] = 0.f;

    const unsigned* Khg = Khi + (size_t)bhx * T_ * 32;
    const unsigned* Klg = Klo + (size_t)bhx * T_ * 32;
    const unsigned* Vbg = Vtg + (size_t)bhx * DH * T_;

    float oacc[4][4];
#pragma unroll
    for (int i = 0; i < 4; i++)
#pragma unroll
        for (int j = 0; j < 4; j++) oacc[i][j] = 0.f;
    float rp0 = 0.f, rp1 = 0.f;

    const int ar = wm * 16 + (lane >> 2);

    for (int kt = 0; kt <= qt; kt++) {
        const int k0 = kt * 64;
        __syncthreads();

        {
            const size_t koff = (size_t)(k0 + r4) * 32 + cp8;
            CP_ASYNC16(smem_u32(&Kh_s[r4 * PST + cp8]),     Khg + koff);
            CP_ASYNC16(smem_u32(&Kh_s[r4 * PST + cp8 + 4]), Khg + koff + 4);
            CP_ASYNC16(smem_u32(&Kl_s[r4 * PST + cp8]),     Klg + koff);
            CP_ASYNC16(smem_u32(&Kl_s[r4 * PST + cp8 + 4]), Klg + koff + 4);
            CP_COMMIT();
            const size_t voff = (size_t)r4 * T_ + k0 + cv16;
            CP_ASYNC16(smem_u32(&Vt_s[r4 * AST + cv16]),      Vbg + voff);
            CP_ASYNC16(smem_u32(&Vt_s[r4 * AST + cv16 + 4]),  Vbg + voff + 4);
            CP_ASYNC16(smem_u32(&Vt_s[r4 * AST + cv16 + 8]),  Vbg + voff + 8);
            CP_ASYNC16(smem_u32(&Vt_s[r4 * AST + cv16 + 12]), Vbg + voff + 12);
            CP_COMMIT();
        }
        CP_WAIT(1);
        __syncthreads();

        float s[4][4];
#pragma unroll
        for (int i = 0; i < 4; i++)
#pragma unroll
            for (int j = 0; j < 4; j++) s[i][j] = 0.f;

#pragma unroll
        for (int st = 0; st < 4; st++) {
            const int g0 = st * 8;
            const unsigned* ahp = &Qh_s[ar * PST + g0 + (lane & 3)];
            const unsigned* alp = &Ql_s[ar * PST + g0 + (lane & 3)];
            unsigned ah[4] = {ahp[0], ahp[8 * PST], ahp[4], ahp[8 * PST + 4]};
            unsigned al[4] = {alp[0], alp[8 * PST], alp[4], alp[8 * PST + 4]};
#pragma unroll
            for (int nf = 0; nf < 4; nf++) {
                const int br = wn * 32 + nf * 8 + (lane >> 2);
                const unsigned* bhp = &Kh_s[br * PST + g0 + (lane & 3)];
                const unsigned* blp = &Kl_s[br * PST + g0 + (lane & 3)];
                unsigned b0 = bhp[0], b1 = bhp[4];
                unsigned c0 = blp[0], c1 = blp[4];
                MMA_BF16(s[nf], ah, b0, b1);
                MMA_BF16(s[nf], ah, c0, c1);
                MMA_BF16(s[nf], al, b0, b1);
            }
        }

        {
            const int qg0 = q0 + ar;
            const bool diag = (kt == qt);
#pragma unroll
            for (int nf = 0; nf < 4; nf++) {
                const int kg0 = k0 + wn * 32 + nf * 8 + (lane & 3) * 2;
                float w[4];
#pragma unroll
                for (int c = 0; c < 4; c++) {
                    const int qg = qg0 + (c >> 1) * 8;
                    const int kg = kg0 + (c & 1);
                    const int rel = kg - qg;
                    float wv = 0.f;
                    if (!diag || rel <= 0) {
                        const int u = max(rel + (MAXREL - 1), 0);
                        wv = fmaxf(fmaf(s[nf][c], 0.125f, bh[u]), 0.f) + 1e-6f;
                    }
                    w[c] = wv;
                }
                rp0 += w[0] + w[1];
                rp1 += w[2] + w[3];
                const int cl = wn * 32 + nf * 8 + (lane & 3) * 2;
                *(uint2*)&Ws_s[ar * AST + cl]       = make_uint2(f2tf32(w[0]), f2tf32(w[1]));
                *(uint2*)&Ws_s[(ar + 8) * AST + cl] = make_uint2(f2tf32(w[2]), f2tf32(w[3]));
            }
        }
        CP_WAIT(0);
        __syncthreads();

#pragma unroll
        for (int ks8 = 0; ks8 < 8; ks8++) {
            const int g0 = ks8 * 8;
            const unsigned* ap = &Ws_s[ar * AST + g0 + (lane & 3)];
            unsigned a[4] = {ap[0], ap[8 * AST], ap[4], ap[8 * AST + 4]};
#pragma unroll
            for (int nf = 0; nf < 4; nf++) {
                const int br = wn * 32 + nf * 8 + (lane >> 2);
                const unsigned* bp = &Vt_s[br * AST + g0 + (lane & 3)];
                MMA_TF32(oacc[nf], a, bp[0], bp[4]);
            }
        }
    }

    rp0 += __shfl_xor_sync(0xffffffffu, rp0, 1);
    rp0 += __shfl_xor_sync(0xffffffffu, rp0, 2);
    rp1 += __shfl_xor_sync(0xffffffffu, rp1, 1);
    rp1 += __shfl_xor_sync(0xffffffffu, rp1, 2);
    if ((lane & 3) == 0) {
        atomicAdd(&rsum[ar], rp0);
        atomicAdd(&rsum[ar + 8], rp1);
    }
    __syncthreads();

    const float inv0 = 1.f / (rsum[ar] + 1e-6f);
    const float inv1 = 1.f / (rsum[ar + 8] + 1e-6f);
#pragma unroll
    for (int nf = 0; nf < 4; nf++) {
        const int d = wn * 32 + nf * 8 + (lane & 3) * 2;
        float* dst0 = out + (size_t)(b * T_ + q0 + ar) * C_ + h * DH + d;
        float* dst1 = out + (size_t)(b * T_ + q0 + ar + 8) * C_ + h * DH + d;
        *(float2*)dst0 = make_float2(oacc[nf][0] * inv0, oacc[nf][1] * inv0);
        *(float2*)dst1 = make_float2(oacc[nf][2] * inv1, oacc[nf][3] * inv1);
    }
}

#define ATTN_SMEM ((4 * 64 * PST + 2 * 64 * AST + 128) * 4)   // 72192 B

// ---------------------------------------------------------------------------
extern "C" void kernel_launch(void* const* d_in, const int* in_sizes, int n_in,
                              void* d_out, int out_size)
{
    const float* x   = (const float*)d_in[0];
    const float* Wq  = (const float*)d_in[2];
    const float* bq  = (const float*)d_in[3];
    const float* Wk  = (const float*)d_in[4];
    const float* bk  = (const float*)d_in[5];
    const float* Wv  = (const float*)d_in[6];
    const float* bv  = (const float*)d_in[7];
    const float* Wo  = (const float*)d_in[8];
    const float* bo  = (const float*)d_in[9];
    const float* rel = (const float*)d_in[10];

    unsigned *qhi, *qlo, *khi, *klo, *vt;
    float* pA;
    cudaGetSymbolAddress((void**)&qhi, g_Qhi);
    cudaGetSymbolAddress((void**)&qlo, g_Qlo);
    cudaGetSymbolAddress((void**)&khi, g_Khi);
    cudaGetSymbolAddress((void**)&klo, g_Klo);
    cudaGetSymbolAddress((void**)&vt,  g_Vt);
    cudaGetSymbolAddress((void**)&pA,  g_att);

    static int configured = 0;
    if (!configured) {
        cudaFuncSetAttribute(attn_v2, cudaFuncAttributeMaxDynamicSharedMemorySize,
                             ATTN_SMEM);
        configured = 1;
    }

    dim3 gg(C_ / 128, (B_ * T_) / 128);  // (8, 32)
    gemm_hc<2><<<gg, 256>>>(x, Wq, bq, nullptr, qhi, qlo);
    gemm_hc<2><<<gg, 256>>>(x, Wk, bk, nullptr, khi, klo);
    gemm_hc<3><<<gg, 256>>>(x, Wv, bv, nullptr, vt, nullptr);

    attn_v2<<<dim3(16, H_, B_), 256, ATTN_SMEM>>>(qhi, qlo, khi, klo, vt, rel, pA);

    gemm_hc<0><<<gg, 256>>>(pA, Wo, bo, (float*)d_out, nullptr, nullptr);
}

// round 8
// speedup vs baseline: 4.0042x; 1.1899x over previous
#include <cuda_runtime.h>
#include <cuda_bf16.h>
#include <cuda_fp16.h>
#include <cstdint>

// Problem constants (fixed by setup_inputs)
#define B_  4
#define T_  1024
#define C_  1024
#define H_  16
#define DH  64
#define MAXREL 32

// Scratch (allocation-free rule: __device__ globals)
__device__ __half  g_x2 [B_*T_*C_];            // x in half
__device__ __half  g_w2q[C_*C_], g_w2k[C_*C_], g_w2v[C_*C_], g_w2o[C_*C_];
__device__ __half  g_ath[B_*T_*C_];            // attention output in half
__device__ unsigned g_Qhi[B_*H_*T_*DH/2], g_Qlo[B_*H_*T_*DH/2];  // bf16x2 pairs
__device__ unsigned g_Khi[B_*H_*T_*DH/2], g_Klo[B_*H_*T_*DH/2];
__device__ unsigned g_Vt [B_*H_*DH*T_];                          // tf32, [B,H,D,T]

__device__ __forceinline__ unsigned f2tf32(float x) {
    unsigned r;
    asm("cvt.rna.tf32.f32 %0, %1;" : "=r"(r) : "f"(x));
    return r;
}
__device__ __forceinline__ uint32_t smem_u32(const void* p) {
    uint32_t a;
    asm("{ .reg .u64 t; cvta.to.shared.u64 t, %1; cvt.u32.u64 %0, t; }"
        : "=r"(a) : "l"(p));
    return a;
}

#define MMA_TF32(acc, a, b0, b1)                                              \
    asm volatile(                                                             \
        "mma.sync.aligned.m16n8k8.row.col.f32.tf32.tf32.f32 "                 \
        "{%0,%1,%2,%3}, {%4,%5,%6,%7}, {%8,%9}, {%0,%1,%2,%3};"               \
        : "+f"(acc[0]), "+f"(acc[1]), "+f"(acc[2]), "+f"(acc[3])              \
        : "r"(a[0]), "r"(a[1]), "r"(a[2]), "r"(a[3]), "r"(b0), "r"(b1))

#define MMA_BF16(acc, a, b0, b1)                                              \
    asm volatile(                                                             \
        "mma.sync.aligned.m16n8k16.row.col.f32.bf16.bf16.f32 "                \
        "{%0,%1,%2,%3}, {%4,%5,%6,%7}, {%8,%9}, {%0,%1,%2,%3};"               \
        : "+f"(acc[0]), "+f"(acc[1]), "+f"(acc[2]), "+f"(acc[3])              \
        : "r"(a[0]), "r"(a[1]), "r"(a[2]), "r"(a[3]), "r"(b0), "r"(b1))

#define MMA_FP16(acc, a, b0, b1)                                              \
    asm volatile(                                                             \
        "mma.sync.aligned.m16n8k16.row.col.f32.f16.f16.f32 "                  \
        "{%0,%1,%2,%3}, {%4,%5,%6,%7}, {%8,%9}, {%0,%1,%2,%3};"               \
        : "+f"(acc[0]), "+f"(acc[1]), "+f"(acc[2]), "+f"(acc[3])              \
        : "r"(a[0]), "r"(a[1]), "r"(a[2]), "r"(a[3]), "r"(b0), "r"(b1))

#define CP_ASYNC16(saddr, gptr)                                               \
    asm volatile("cp.async.cg.shared.global [%0], [%1], 16;"                  \
                 :: "r"(saddr), "l"(gptr) : "memory")
#define CP_COMMIT()      asm volatile("cp.async.commit_group;" ::: "memory")
#define CP_WAIT(n)       asm volatile("cp.async.wait_group %0;" :: "n"(n) : "memory")

// ---------------------------------------------------------------------------
// f32 -> half conversion (one-time, removes cvt + fp32 loads from GEMM loop)
// ---------------------------------------------------------------------------
__global__ void cvt_half(const float* __restrict__ in, __half* __restrict__ out,
                         int n)
{
    const int i = (blockIdx.x * blockDim.x + threadIdx.x) * 8;
    if (i >= n) return;
    float4 v0 = *(const float4*)(in + i);
    float4 v1 = *(const float4*)(in + i + 4);
    __half2 h[4] = {__floats2half2_rn(v0.x, v0.y), __floats2half2_rn(v0.z, v0.w),
                    __floats2half2_rn(v1.x, v1.y), __floats2half2_rn(v1.z, v1.w)};
    *(uint4*)(out + i) = *(uint4*)h;
}

// ---------------------------------------------------------------------------
// fp16 GEMM, cp.async 3-stage pipeline: C = A[M,K] @ W[N,K]^T + bias[N].
// BM=BN=128, BK=32. 256 threads (8 warps 2x4), warp tile 64x32.
// A, W are pre-converted half. smem row = 32 halves (16 u32), stride 20.
// MODE 0: C row-major [M,N] fp32
// MODE 2: packed bf16 hi/lo pairs out, layout [B,H,T,DH/2]  (Q, K)
// MODE 3: tf32 u32 out, transposed layout [B,H,DH,T]        (V)
// ---------------------------------------------------------------------------
#define GST   20
#define STG_U (128 * GST)          // u32 per tile (A or B)
#define GEMM_SMEM (3 * 2 * STG_U * 4)   // 61440 B

__device__ __forceinline__ void store_hilo(unsigned* Phi, unsigned* Plo, size_t off,
                                           float x, float y) {
    __nv_bfloat16 hx = __float2bfloat16(x), hy = __float2bfloat16(y);
    __nv_bfloat162 h2(hx, hy);
    __nv_bfloat162 l2(__float2bfloat16(x - __bfloat162float(hx)),
                      __float2bfloat16(y - __bfloat162float(hy)));
    Phi[off] = *(unsigned*)&h2;
    Plo[off] = *(unsigned*)&l2;
}

template<int MODE>
__global__ void __launch_bounds__(256, 2)
gemm_h2(const __half* __restrict__ A, const __half* __restrict__ W,
        const float* __restrict__ bias, float* __restrict__ C,
        unsigned* __restrict__ Phi, unsigned* __restrict__ Plo)
{
    const int K = 1024, N = 1024;
    extern __shared__ unsigned sm[];

    const int t = threadIdx.x;
    const int lane = t & 31, warp = t >> 5;
    const int wm = warp >> 2, wn = warp & 3;
    const int m0 = blockIdx.y * 128, n0 = blockIdx.x * 128;

    const int r   = t >> 1;       // 0..127
    const int seg = t & 1;        // 32B half-row
    const __half* Ap = A + (size_t)(m0 + r) * K + seg * 16;
    const __half* Wp = W + (size_t)(n0 + r) * K + seg * 16;
    const uint32_t dstA = smem_u32(sm) + (r * GST + seg * 8) * 4;
    const uint32_t dstB = dstA + STG_U * 4;

    auto issue = [&](int kt) {
        const uint32_t sb = (kt % 3) * (2 * STG_U * 4);
        const __half* a = Ap + kt * 32;
        const __half* b = Wp + kt * 32;
        CP_ASYNC16(dstA + sb,      a);
        CP_ASYNC16(dstA + sb + 16, a + 8);
        CP_ASYNC16(dstB + sb,      b);
        CP_ASYNC16(dstB + sb + 16, b + 8);
    };

    float acc[4][4][4];
#pragma unroll
    for (int i = 0; i < 4; i++)
#pragma unroll
        for (int j = 0; j < 4; j++)
#pragma unroll
            for (int x = 0; x < 4; x++) acc[i][j][x] = 0.f;

    issue(0); CP_COMMIT();
    issue(1); CP_COMMIT();

    const int NKT = K / 32;   // 32
    for (int kt = 0; kt < NKT; kt++) {
        if (kt + 2 < NKT) issue(kt + 2);
        CP_COMMIT();
        CP_WAIT(2);
        __syncthreads();

        const unsigned* Sa = sm + (kt % 3) * 2 * STG_U;
        const unsigned* Sb = Sa + STG_U;
#pragma unroll
        for (int s = 0; s < 2; s++) {
            const int g0 = s * 8;
            unsigned af[4][4], bf[4][2];
#pragma unroll
            for (int mf = 0; mf < 4; mf++) {
                const int rr = wm * 64 + mf * 16 + (lane >> 2);
                const unsigned* p = &Sa[rr * GST + g0 + (lane & 3)];
                af[mf][0] = p[0];
                af[mf][1] = p[8 * GST];
                af[mf][2] = p[4];
                af[mf][3] = p[8 * GST + 4];
            }
#pragma unroll
            for (int nf = 0; nf < 4; nf++) {
                const int rr = wn * 32 + nf * 8 + (lane >> 2);
                const unsigned* p = &Sb[rr * GST + g0 + (lane & 3)];
                bf[nf][0] = p[0];
                bf[nf][1] = p[4];
            }
#pragma unroll
            for (int mf = 0; mf < 4; mf++)
#pragma unroll
                for (int nf = 0; nf < 4; nf++)
                    MMA_FP16(acc[mf][nf], af[mf], bf[nf][0], bf[nf][1]);
        }
        __syncthreads();
    }

    // epilogue
#pragma unroll
    for (int nf = 0; nf < 4; nf++) {
        const int col = n0 + wn * 32 + nf * 8 + (lane & 3) * 2;
        const float bv0 = bias[col], bv1 = bias[col + 1];
#pragma unroll
        for (int mf = 0; mf < 4; mf++) {
            const int row = m0 + wm * 64 + mf * 16 + (lane >> 2);
            float2 v0 = make_float2(acc[mf][nf][0] + bv0, acc[mf][nf][1] + bv1);
            float2 v1 = make_float2(acc[mf][nf][2] + bv0, acc[mf][nf][3] + bv1);
            if (MODE == 0) {
                *(float2*)(C + (size_t)row * N + col)       = v0;
                *(float2*)(C + (size_t)(row + 8) * N + col) = v1;
            } else if (MODE == 2) {
                const int h = col >> 6, d = col & 63, pr = d >> 1;
                const int bb = row >> 10, tt = row & 1023;
                const size_t off = ((((size_t)bb * H_ + h) * T_ + tt) * 32) + pr;
                store_hilo(Phi, Plo, off,          v0.x, v0.y);
                store_hilo(Phi, Plo, off + 8 * 32, v1.x, v1.y);
            } else {  // MODE 3: V transposed tf32 [B,H,D,T]
                const int h = col >> 6, d = col & 63;
                const int bb = row >> 10, tt = row & 1023;
                const size_t vb = (((size_t)bb * H_ + h) * DH + d) * T_ + tt;
                Phi[vb]          = f2tf32(v0.x);
                Phi[vb + T_]     = f2tf32(v0.y);
                Phi[vb + 8]      = f2tf32(v1.x);
                Phi[vb + T_ + 8] = f2tf32(v1.y);
            }
        }
    }
}

// ---------------------------------------------------------------------------
// Fused causal algebraic attention (round 5 structure; now writes half out).
// ---------------------------------------------------------------------------
#define PST 36
#define AST 68

__global__ void __launch_bounds__(256, 3)
attn_v2(const unsigned* __restrict__ Qhi, const unsigned* __restrict__ Qlo,
        const unsigned* __restrict__ Khi, const unsigned* __restrict__ Klo,
        const unsigned* __restrict__ Vtg, const float* __restrict__ rel_bias,
        __half* __restrict__ out)
{
    extern __shared__ unsigned sm[];
    unsigned* Qh_s = sm;
    unsigned* Ql_s = Qh_s + 64 * PST;
    unsigned* Kh_s = Ql_s + 64 * PST;
    unsigned* Kl_s = Kh_s + 64 * PST;
    unsigned* Vt_s = Kl_s + 64 * PST;
    unsigned* Ws_s = Vt_s + 64 * AST;
    float* bh   = (float*)(Ws_s + 64 * AST);
    float* rsum = bh + 64;

    const int qt = 15 - (int)blockIdx.x;
    const int h  = blockIdx.y;
    const int b  = blockIdx.z;
    const int t  = threadIdx.x;
    const int lane = t & 31, warp = t >> 5;
    const int wm = warp >> 1, wn = warp & 1;
    const int q0 = qt * 64;
    const int bhx = b * H_ + h;

    const int r4   = t >> 2;
    const int cp8  = (t & 3) * 8;
    const int cv16 = (t & 3) * 16;

    {
        const size_t qoff = ((size_t)bhx * T_ + q0 + r4) * 32 + cp8;
        CP_ASYNC16(smem_u32(&Qh_s[r4 * PST + cp8]),     Qhi + qoff);
        CP_ASYNC16(smem_u32(&Qh_s[r4 * PST + cp8 + 4]), Qhi + qoff + 4);
        CP_ASYNC16(smem_u32(&Ql_s[r4 * PST + cp8]),     Qlo + qoff);
        CP_ASYNC16(smem_u32(&Ql_s[r4 * PST + cp8 + 4]), Qlo + qoff + 4);
        CP_COMMIT();
    }
    if (t < 2 * MAXREL - 1) bh[t] = rel_bias[t * H_ + h];
    if (t < 64) rsum[t] = 0.f;

    const unsigned* Khg = Khi + (size_t)bhx * T_ * 32;
    const unsigned* Klg = Klo + (size_t)bhx * T_ * 32;
    const unsigned* Vbg = Vtg + (size_t)bhx * DH * T_;

    float oacc[4][4];
#pragma unroll
    for (int i = 0; i < 4; i++)
#pragma unroll
        for (int j = 0; j < 4; j++) oacc[i][j] = 0.f;
    float rp0 = 0.f, rp1 = 0.f;

    const int ar = wm * 16 + (lane >> 2);

    for (int kt = 0; kt <= qt; kt++) {
        const int k0 = kt * 64;
        __syncthreads();

        {
            const size_t koff = (size_t)(k0 + r4) * 32 + cp8;
            CP_ASYNC16(smem_u32(&Kh_s[r4 * PST + cp8]),     Khg + koff);
            CP_ASYNC16(smem_u32(&Kh_s[r4 * PST + cp8 + 4]), Khg + koff + 4);
            CP_ASYNC16(smem_u32(&Kl_s[r4 * PST + cp8]),     Klg + koff);
            CP_ASYNC16(smem_u32(&Kl_s[r4 * PST + cp8 + 4]), Klg + koff + 4);
            CP_COMMIT();
            const size_t voff = (size_t)r4 * T_ + k0 + cv16;
            CP_ASYNC16(smem_u32(&Vt_s[r4 * AST + cv16]),      Vbg + voff);
            CP_ASYNC16(smem_u32(&Vt_s[r4 * AST + cv16 + 4]),  Vbg + voff + 4);
            CP_ASYNC16(smem_u32(&Vt_s[r4 * AST + cv16 + 8]),  Vbg + voff + 8);
            CP_ASYNC16(smem_u32(&Vt_s[r4 * AST + cv16 + 12]), Vbg + voff + 12);
            CP_COMMIT();
        }
        CP_WAIT(1);
        __syncthreads();

        float s[4][4];
#pragma unroll
        for (int i = 0; i < 4; i++)
#pragma unroll
            for (int j = 0; j < 4; j++) s[i][j] = 0.f;

#pragma unroll
        for (int st = 0; st < 4; st++) {
            const int g0 = st * 8;
            const unsigned* ahp = &Qh_s[ar * PST + g0 + (lane & 3)];
            const unsigned* alp = &Ql_s[ar * PST + g0 + (lane & 3)];
            unsigned ah[4] = {ahp[0], ahp[8 * PST], ahp[4], ahp[8 * PST + 4]};
            unsigned al[4] = {alp[0], alp[8 * PST], alp[4], alp[8 * PST + 4]};
#pragma unroll
            for (int nf = 0; nf < 4; nf++) {
                const int br = wn * 32 + nf * 8 + (lane >> 2);
                const unsigned* bhp = &Kh_s[br * PST + g0 + (lane & 3)];
                const unsigned* blp = &Kl_s[br * PST + g0 + (lane & 3)];
                unsigned b0 = bhp[0], b1 = bhp[4];
                unsigned c0 = blp[0], c1 = blp[4];
                MMA_BF16(s[nf], ah, b0, b1);
                MMA_BF16(s[nf], ah, c0, c1);
                MMA_BF16(s[nf], al, b0, b1);
            }
        }

        {
            const int qg0 = q0 + ar;
            const bool diag = (kt == qt);
#pragma unroll
            for (int nf = 0; nf < 4; nf++) {
                const int kg0 = k0 + wn * 32 + nf * 8 + (lane & 3) * 2;
                float w[4];
#pragma unroll
                for (int c = 0; c < 4; c++) {
                    const int qg = qg0 + (c >> 1) * 8;
                    const int kg = kg0 + (c & 1);
                    const int rel = kg - qg;
                    float wv = 0.f;
                    if (!diag || rel <= 0) {
                        const int u = max(rel + (MAXREL - 1), 0);
                        wv = fmaxf(fmaf(s[nf][c], 0.125f, bh[u]), 0.f) + 1e-6f;
                    }
                    w[c] = wv;
                }
                rp0 += w[0] + w[1];
                rp1 += w[2] + w[3];
                const int cl = wn * 32 + nf * 8 + (lane & 3) * 2;
                *(uint2*)&Ws_s[ar * AST + cl]       = make_uint2(f2tf32(w[0]), f2tf32(w[1]));
                *(uint2*)&Ws_s[(ar + 8) * AST + cl] = make_uint2(f2tf32(w[2]), f2tf32(w[3]));
            }
        }
        CP_WAIT(0);
        __syncthreads();

#pragma unroll
        for (int ks8 = 0; ks8 < 8; ks8++) {
            const int g0 = ks8 * 8;
            const unsigned* ap = &Ws_s[ar * AST + g0 + (lane & 3)];
            unsigned a[4] = {ap[0], ap[8 * AST], ap[4], ap[8 * AST + 4]};
#pragma unroll
            for (int nf = 0; nf < 4; nf++) {
                const int br = wn * 32 + nf * 8 + (lane >> 2);
                const unsigned* bp = &Vt_s[br * AST + g0 + (lane & 3)];
                MMA_TF32(oacc[nf], a, bp[0], bp[4]);
            }
        }
    }

    rp0 += __shfl_xor_sync(0xffffffffu, rp0, 1);
    rp0 += __shfl_xor_sync(0xffffffffu, rp0, 2);
    rp1 += __shfl_xor_sync(0xffffffffu, rp1, 1);
    rp1 += __shfl_xor_sync(0xffffffffu, rp1, 2);
    if ((lane & 3) == 0) {
        atomicAdd(&rsum[ar], rp0);
        atomicAdd(&rsum[ar + 8], rp1);
    }
    __syncthreads();

    const float inv0 = 1.f / (rsum[ar] + 1e-6f);
    const float inv1 = 1.f / (rsum[ar + 8] + 1e-6f);
#pragma unroll
    for (int nf = 0; nf < 4; nf++) {
        const int d = wn * 32 + nf * 8 + (lane & 3) * 2;
        __half* dst0 = out + (size_t)(b * T_ + q0 + ar) * C_ + h * DH + d;
        __half* dst1 = out + (size_t)(b * T_ + q0 + ar + 8) * C_ + h * DH + d;
        __half2 h0 = __floats2half2_rn(oacc[nf][0] * inv0, oacc[nf][1] * inv0);
        __half2 h1 = __floats2half2_rn(oacc[nf][2] * inv1, oacc[nf][3] * inv1);
        *(__half2*)dst0 = h0;
        *(__half2*)dst1 = h1;
    }
}

#define ATTN_SMEM ((4 * 64 * PST + 2 * 64 * AST + 128) * 4)   // 72192 B

// ---------------------------------------------------------------------------
extern "C" void kernel_launch(void* const* d_in, const int* in_sizes, int n_in,
                              void* d_out, int out_size)
{
    const float* x   = (const float*)d_in[0];
    const float* Wq  = (const float*)d_in[2];
    const float* bq  = (const float*)d_in[3];
    const float* Wk  = (const float*)d_in[4];
    const float* bk  = (const float*)d_in[5];
    const float* Wv  = (const float*)d_in[6];
    const float* bv  = (const float*)d_in[7];
    const float* Wo  = (const float*)d_in[8];
    const float* bo  = (const float*)d_in[9];
    const float* rel = (const float*)d_in[10];

    __half *x2, *w2q, *w2k, *w2v, *w2o, *ath;
    unsigned *qhi, *qlo, *khi, *klo, *vt;
    cudaGetSymbolAddress((void**)&x2,  g_x2);
    cudaGetSymbolAddress((void**)&w2q, g_w2q);
    cudaGetSymbolAddress((void**)&w2k, g_w2k);
    cudaGetSymbolAddress((void**)&w2v, g_w2v);
    cudaGetSymbolAddress((void**)&w2o, g_w2o);
    cudaGetSymbolAddress((void**)&ath, g_ath);
    cudaGetSymbolAddress((void**)&qhi, g_Qhi);
    cudaGetSymbolAddress((void**)&qlo, g_Qlo);
    cudaGetSymbolAddress((void**)&khi, g_Khi);
    cudaGetSymbolAddress((void**)&klo, g_Klo);
    cudaGetSymbolAddress((void**)&vt,  g_Vt);

    static int configured = 0;
    if (!configured) {
        cudaFuncSetAttribute(attn_v2, cudaFuncAttributeMaxDynamicSharedMemorySize,
                             ATTN_SMEM);
        cudaFuncSetAttribute(gemm_h2<0>, cudaFuncAttributeMaxDynamicSharedMemorySize,
                             GEMM_SMEM);
        cudaFuncSetAttribute(gemm_h2<2>, cudaFuncAttributeMaxDynamicSharedMemorySize,
                             GEMM_SMEM);
        cudaFuncSetAttribute(gemm_h2<3>, cudaFuncAttributeMaxDynamicSharedMemorySize,
                             GEMM_SMEM);
        configured = 1;
    }

    const int NX = B_ * T_ * C_, NW = C_ * C_;
    cvt_half<<<NX / 2048, 256>>>(x,  x2,  NX);
    cvt_half<<<NW / 2048, 256>>>(Wq, w2q, NW);
    cvt_half<<<NW / 2048, 256>>>(Wk, w2k, NW);
    cvt_half<<<NW / 2048, 256>>>(Wv, w2v, NW);
    cvt_half<<<NW / 2048, 256>>>(Wo, w2o, NW);

    dim3 gg(C_ / 128, (B_ * T_) / 128);  // (8, 32)
    gemm_h2<2><<<gg, 256, GEMM_SMEM>>>(x2, w2q, bq, nullptr, qhi, qlo);
    gemm_h2<2><<<gg, 256, GEMM_SMEM>>>(x2, w2k, bk, nullptr, khi, klo);
    gemm_h2<3><<<gg, 256, GEMM_SMEM>>>(x2, w2v, bv, nullptr, vt, nullptr);

    attn_v2<<<dim3(16, H_, B_), 256, ATTN_SMEM>>>(qhi, qlo, khi, klo, vt, rel, ath);

    gemm_h2<0><<<gg, 256, GEMM_SMEM>>>(ath, w2o, bo, (float*)d_out, nullptr, nullptr);
}

// round 10
// speedup vs baseline: 4.7316x; 1.1817x over previous
#include <cuda_runtime.h>
#include <cuda_bf16.h>
#include <cuda_fp16.h>
#include <cstdint>

// Problem constants (fixed by setup_inputs)
#define B_  4
#define T_  1024
#define C_  1024
#define H_  16
#define DH  64
#define MAXREL 32

// W-scale: keeps relu(..)+1e-6 weights inside fp16 normal range.
// out = (sum (S*w) V) / (S * (rsum + 1e-6)) is algebraically identical.
#define WSCALE 256.0f
#define WSCALE_INV (1.0f / 256.0f)

// Scratch (allocation-free rule: __device__ globals)
__device__ __half  g_x2 [B_*T_*C_];            // x in half
__device__ __half  g_w2q[C_*C_], g_w2k[C_*C_], g_w2v[C_*C_], g_w2o[C_*C_];
__device__ __half  g_ath[B_*T_*C_];            // attention output in half
__device__ __half  g_Vth[B_*H_*DH*T_];         // V in half, [B,H,D,T]
__device__ unsigned g_Qhi[B_*H_*T_*DH/2], g_Qlo[B_*H_*T_*DH/2];  // bf16x2 pairs
__device__ unsigned g_Khi[B_*H_*T_*DH/2], g_Klo[B_*H_*T_*DH/2];

__device__ __forceinline__ uint32_t smem_u32(const void* p) {
    uint32_t a;
    asm("{ .reg .u64 t; cvta.to.shared.u64 t, %1; cvt.u32.u64 %0, t; }"
        : "=r"(a) : "l"(p));
    return a;
}

#define MMA_BF16(acc, a, b0, b1)                                              \
    asm volatile(                                                             \
        "mma.sync.aligned.m16n8k16.row.col.f32.bf16.bf16.f32 "                \
        "{%0,%1,%2,%3}, {%4,%5,%6,%7}, {%8,%9}, {%0,%1,%2,%3};"               \
        : "+f"(acc[0]), "+f"(acc[1]), "+f"(acc[2]), "+f"(acc[3])              \
        : "r"(a[0]), "r"(a[1]), "r"(a[2]), "r"(a[3]), "r"(b0), "r"(b1))

#define MMA_FP16(acc, a, b0, b1)                                              \
    asm volatile(                                                             \
        "mma.sync.aligned.m16n8k16.row.col.f32.f16.f16.f32 "                  \
        "{%0,%1,%2,%3}, {%4,%5,%6,%7}, {%8,%9}, {%0,%1,%2,%3};"               \
        : "+f"(acc[0]), "+f"(acc[1]), "+f"(acc[2]), "+f"(acc[3])              \
        : "r"(a[0]), "r"(a[1]), "r"(a[2]), "r"(a[3]), "r"(b0), "r"(b1))

#define CP_ASYNC16(saddr, gptr)                                               \
    asm volatile("cp.async.cg.shared.global [%0], [%1], 16;"                  \
                 :: "r"(saddr), "l"(gptr) : "memory")
#define CP_COMMIT()      asm volatile("cp.async.commit_group;" ::: "memory")
#define CP_WAIT(n)       asm volatile("cp.async.wait_group %0;" :: "n"(n) : "memory")

// ---------------------------------------------------------------------------
// f32 -> half conversion (one-time)
// ---------------------------------------------------------------------------
__global__ void cvt_half(const float* __restrict__ in, __half* __restrict__ out,
                         int n)
{
    const int i = (blockIdx.x * blockDim.x + threadIdx.x) * 8;
    if (i >= n) return;
    float4 v0 = *(const float4*)(in + i);
    float4 v1 = *(const float4*)(in + i + 4);
    __half2 h[4] = {__floats2half2_rn(v0.x, v0.y), __floats2half2_rn(v0.z, v0.w),
                    __floats2half2_rn(v1.x, v1.y), __floats2half2_rn(v1.z, v1.w)};
    *(uint4*)(out + i) = *(uint4*)h;
}

// ---------------------------------------------------------------------------
// fp16 GEMM, cp.async 3-stage, ONE barrier per k-iter.
// C = A[M,K] @ W[N,K]^T + bias[N]. BM=BN=128, BK=32, 256 thr (8 warps 2x4).
// MODE 0: C row-major [M,N] fp32
// MODE 2: packed bf16 hi/lo pairs out, [B,H,T,DH/2]   (Q, K)
// MODE 3: half out, transposed [B,H,DH,T]             (V)
// ---------------------------------------------------------------------------
#define GST   20
#define STG_U (128 * GST)
#define GEMM_SMEM (3 * 2 * STG_U * 4)   // 61440 B

__device__ __forceinline__ void store_hilo(unsigned* Phi, unsigned* Plo, size_t off,
                                           float x, float y) {
    __nv_bfloat16 hx = __float2bfloat16(x), hy = __float2bfloat16(y);
    __nv_bfloat162 h2(hx, hy);
    __nv_bfloat162 l2(__float2bfloat16(x - __bfloat162float(hx)),
                      __float2bfloat16(y - __bfloat162float(hy)));
    Phi[off] = *(unsigned*)&h2;
    Plo[off] = *(unsigned*)&l2;
}

template<int MODE>
__global__ void __launch_bounds__(256, 2)
gemm_h2(const __half* __restrict__ A, const __half* __restrict__ W,
        const float* __restrict__ bias, float* __restrict__ C,
        unsigned* __restrict__ Phi, unsigned* __restrict__ Plo,
        __half* __restrict__ Vh)
{
    const int K = 1024, N = 1024;
    extern __shared__ unsigned sm[];

    const int t = threadIdx.x;
    const int lane = t & 31, warp = t >> 5;
    const int wm = warp >> 2, wn = warp & 3;
    const int m0 = blockIdx.y * 128, n0 = blockIdx.x * 128;

    const int r   = t >> 1;
    const int seg = t & 1;
    const __half* Ap = A + (size_t)(m0 + r) * K + seg * 16;
    const __half* Wp = W + (size_t)(n0 + r) * K + seg * 16;
    const uint32_t dstA = smem_u32(sm) + (r * GST + seg * 8) * 4;
    const uint32_t dstB = dstA + STG_U * 4;

    auto issue = [&](int kt) {
        const uint32_t sb = (kt % 3) * (2 * STG_U * 4);
        const __half* a = Ap + kt * 32;
        const __half* b = Wp + kt * 32;
        CP_ASYNC16(dstA + sb,      a);
        CP_ASYNC16(dstA + sb + 16, a + 8);
        CP_ASYNC16(dstB + sb,      b);
        CP_ASYNC16(dstB + sb + 16, b + 8);
        CP_COMMIT();
    };

    float acc[4][4][4];
#pragma unroll
    for (int i = 0; i < 4; i++)
#pragma unroll
        for (int j = 0; j < 4; j++)
#pragma unroll
            for (int x = 0; x < 4; x++) acc[i][j][x] = 0.f;

    issue(0);
    issue(1);

    const int NKT = K / 32;   // 32
    for (int kt = 0; kt < NKT; kt++) {
        CP_WAIT(1);
        __syncthreads();

        const unsigned* Sa = sm + (kt % 3) * 2 * STG_U;
        const unsigned* Sb = Sa + STG_U;
#pragma unroll
        for (int s = 0; s < 2; s++) {
            const int g0 = s * 8;
            unsigned af[4][4], bf[4][2];
#pragma unroll
            for (int mf = 0; mf < 4; mf++) {
                const int rr = wm * 64 + mf * 16 + (lane >> 2);
                const unsigned* p = &Sa[rr * GST + g0 + (lane & 3)];
                af[mf][0] = p[0];
                af[mf][1] = p[8 * GST];
                af[mf][2] = p[4];
                af[mf][3] = p[8 * GST + 4];
            }
#pragma unroll
            for (int nf = 0; nf < 4; nf++) {
                const int rr = wn * 32 + nf * 8 + (lane >> 2);
                const unsigned* p = &Sb[rr * GST + g0 + (lane & 3)];
                bf[nf][0] = p[0];
                bf[nf][1] = p[4];
            }
#pragma unroll
            for (int mf = 0; mf < 4; mf++)
#pragma unroll
                for (int nf = 0; nf < 4; nf++)
                    MMA_FP16(acc[mf][nf], af[mf], bf[nf][0], bf[nf][1]);
        }
        // issue AFTER compute: write target (kt+2)%3 was last read at kt-1,
        // and every thread passed sync(kt) only after finishing compute(kt-1).
        if (kt + 2 < NKT) issue(kt + 2);
    }

    // epilogue
#pragma unroll
    for (int nf = 0; nf < 4; nf++) {
        const int col = n0 + wn * 32 + nf * 8 + (lane & 3) * 2;
        const float bv0 = bias[col], bv1 = bias[col + 1];
#pragma unroll
        for (int mf = 0; mf < 4; mf++) {
            const int row = m0 + wm * 64 + mf * 16 + (lane >> 2);
            float2 v0 = make_float2(acc[mf][nf][0] + bv0, acc[mf][nf][1] + bv1);
            float2 v1 = make_float2(acc[mf][nf][2] + bv0, acc[mf][nf][3] + bv1);
            if (MODE == 0) {
                *(float2*)(C + (size_t)row * N + col)       = v0;
                *(float2*)(C + (size_t)(row + 8) * N + col) = v1;
            } else if (MODE == 2) {
                const int h = col >> 6, d = col & 63, pr = d >> 1;
                const int bb = row >> 10, tt = row & 1023;
                const size_t off = ((((size_t)bb * H_ + h) * T_ + tt) * 32) + pr;
                store_hilo(Phi, Plo, off,          v0.x, v0.y);
                store_hilo(Phi, Plo, off + 8 * 32, v1.x, v1.y);
            } else {  // MODE 3: V half, transposed [B,H,D,T]
                const int h = col >> 6, d = col & 63;
                const int bb = row >> 10, tt = row & 1023;
                const size_t vb = (((size_t)bb * H_ + h) * DH + d) * T_ + tt;
                Vh[vb]          = __float2half(v0.x);
                Vh[vb + T_]     = __float2half(v0.y);
                Vh[vb + 8]      = __float2half(v1.x);
                Vh[vb + T_ + 8] = __float2half(v1.y);
            }
        }
    }
}

// ---------------------------------------------------------------------------
// Fused causal algebraic attention v3 (with WSCALE fix).
//   Stage1: S = Q @ K^T, bf16 hi/lo 3-term k16 (48 MMA/tile)
//   Stage2: O += (S*W) @ V, fp16 k16 (16 MMA/tile); normalization folds 1/S.
// All tiles 64 rows x 32 u32 (stride 36). smem 55.8 KB -> 3 CTA/SM.
// ---------------------------------------------------------------------------
#define PST 36

__global__ void __launch_bounds__(256, 3)
attn_v3(const unsigned* __restrict__ Qhi, const unsigned* __restrict__ Qlo,
        const unsigned* __restrict__ Khi, const unsigned* __restrict__ Klo,
        const __half* __restrict__ Vtg, const float* __restrict__ rel_bias,
        __half* __restrict__ out)
{
    extern __shared__ unsigned sm[];
    unsigned* Qh_s = sm;
    unsigned* Ql_s = Qh_s + 64 * PST;
    unsigned* Kh_s = Ql_s + 64 * PST;
    unsigned* Kl_s = Kh_s + 64 * PST;
    unsigned* Vt_s = Kl_s + 64 * PST;   // half [d][t]: 64 rows x 32 u32
    unsigned* Ws_s = Vt_s + 64 * PST;   // half [q][k]: 64 rows x 32 u32
    float* bh   = (float*)(Ws_s + 64 * PST);
    float* rsum = bh + 64;

    const int qt = 15 - (int)blockIdx.x;
    const int h  = blockIdx.y;
    const int b  = blockIdx.z;
    const int t  = threadIdx.x;
    const int lane = t & 31, warp = t >> 5;
    const int wm = warp >> 1, wn = warp & 1;
    const int q0 = qt * 64;
    const int bhx = b * H_ + h;

    const int r4  = t >> 2;
    const int cp8 = (t & 3) * 8;

    {
        const size_t qoff = ((size_t)bhx * T_ + q0 + r4) * 32 + cp8;
        CP_ASYNC16(smem_u32(&Qh_s[r4 * PST + cp8]),     Qhi + qoff);
        CP_ASYNC16(smem_u32(&Qh_s[r4 * PST + cp8 + 4]), Qhi + qoff + 4);
        CP_ASYNC16(smem_u32(&Ql_s[r4 * PST + cp8]),     Qlo + qoff);
        CP_ASYNC16(smem_u32(&Ql_s[r4 * PST + cp8 + 4]), Qlo + qoff + 4);
        CP_COMMIT();
    }
    if (t < 2 * MAXREL - 1) bh[t] = rel_bias[t * H_ + h];
    if (t < 64) rsum[t] = 0.f;

    const unsigned* Khg = Khi + (size_t)bhx * T_ * 32;
    const unsigned* Klg = Klo + (size_t)bhx * T_ * 32;
    const __half*   Vbg = Vtg + (size_t)bhx * DH * T_;

    float oacc[4][4];
#pragma unroll
    for (int i = 0; i < 4; i++)
#pragma unroll
        for (int j = 0; j < 4; j++) oacc[i][j] = 0.f;
    float rp0 = 0.f, rp1 = 0.f;

    const int ar = wm * 16 + (lane >> 2);

    for (int kt = 0; kt <= qt; kt++) {
        const int k0 = kt * 64;
        __syncthreads();

        {
            const size_t koff = (size_t)(k0 + r4) * 32 + cp8;
            CP_ASYNC16(smem_u32(&Kh_s[r4 * PST + cp8]),     Khg + koff);
            CP_ASYNC16(smem_u32(&Kh_s[r4 * PST + cp8 + 4]), Khg + koff + 4);
            CP_ASYNC16(smem_u32(&Kl_s[r4 * PST + cp8]),     Klg + koff);
            CP_ASYNC16(smem_u32(&Kl_s[r4 * PST + cp8 + 4]), Klg + koff + 4);
            CP_COMMIT();
            // V tile: row d = r4, 64 halves of t -> 4 thr x 2 x 16B
            const __half* vp = Vbg + (size_t)r4 * T_ + k0 + (t & 3) * 16;
            CP_ASYNC16(smem_u32(&Vt_s[r4 * PST + cp8]),     vp);
            CP_ASYNC16(smem_u32(&Vt_s[r4 * PST + cp8 + 4]), vp + 8);
            CP_COMMIT();
        }
        CP_WAIT(1);
        __syncthreads();

        // Stage 1: bf16 3-term
        float s[4][4];
#pragma unroll
        for (int i = 0; i < 4; i++)
#pragma unroll
            for (int j = 0; j < 4; j++) s[i][j] = 0.f;

#pragma unroll
        for (int st = 0; st < 4; st++) {
            const int g0 = st * 8;
            const unsigned* ahp = &Qh_s[ar * PST + g0 + (lane & 3)];
            const unsigned* alp = &Ql_s[ar * PST + g0 + (lane & 3)];
            unsigned ah[4] = {ahp[0], ahp[8 * PST], ahp[4], ahp[8 * PST + 4]};
            unsigned al[4] = {alp[0], alp[8 * PST], alp[4], alp[8 * PST + 4]};
#pragma unroll
            for (int nf = 0; nf < 4; nf++) {
                const int br = wn * 32 + nf * 8 + (lane >> 2);
                const unsigned* bhp = &Kh_s[br * PST + g0 + (lane & 3)];
                const unsigned* blp = &Kl_s[br * PST + g0 + (lane & 3)];
                unsigned b0 = bhp[0], b1 = bhp[4];
                unsigned c0 = blp[0], c1 = blp[4];
                MMA_BF16(s[nf], ah, b0, b1);
                MMA_BF16(s[nf], ah, c0, c1);
                MMA_BF16(s[nf], al, b0, b1);
            }
        }

        // Epilogue -> W (half, scaled by WSCALE) + rsum (unscaled, fp32)
        {
            const int qg0 = q0 + ar;
            const bool diag = (kt == qt);
#pragma unroll
            for (int nf = 0; nf < 4; nf++) {
                const int kg0 = k0 + wn * 32 + nf * 8 + (lane & 3) * 2;
                float w[4];
#pragma unroll
                for (int c = 0; c < 4; c++) {
                    const int qg = qg0 + (c >> 1) * 8;
                    const int kg = kg0 + (c & 1);
                    const int rel = kg - qg;
                    float wv = 0.f;
                    if (!diag || rel <= 0) {
                        const int u = max(rel + (MAXREL - 1), 0);
                        wv = fmaxf(fmaf(s[nf][c], 0.125f, bh[u]), 0.f) + 1e-6f;
                    }
                    w[c] = wv;
                }
                rp0 += w[0] + w[1];
                rp1 += w[2] + w[3];
                const int pc = wn * 16 + nf * 4 + (lane & 3);   // pair col
                __half2 h0 = __floats2half2_rn(w[0] * WSCALE, w[1] * WSCALE);
                __half2 h1 = __floats2half2_rn(w[2] * WSCALE, w[3] * WSCALE);
                Ws_s[ar * PST + pc]       = *(unsigned*)&h0;
                Ws_s[(ar + 8) * PST + pc] = *(unsigned*)&h1;
            }
        }
        CP_WAIT(0);
        __syncthreads();

        // Stage 2: O += W @ V, fp16 k16
#pragma unroll
        for (int st = 0; st < 4; st++) {
            const int g0 = st * 8;
            const unsigned* ap = &Ws_s[ar * PST + g0 + (lane & 3)];
            unsigned a[4] = {ap[0], ap[8 * PST], ap[4], ap[8 * PST + 4]};
#pragma unroll
            for (int nf = 0; nf < 4; nf++) {
                const int br = wn * 32 + nf * 8 + (lane >> 2);
                const unsigned* bp = &Vt_s[br * PST + g0 + (lane & 3)];
                MMA_FP16(oacc[nf], a, bp[0], bp[4]);
            }
        }
    }

    rp0 += __shfl_xor_sync(0xffffffffu, rp0, 1);
    rp0 += __shfl_xor_sync(0xffffffffu, rp0, 2);
    rp1 += __shfl_xor_sync(0xffffffffu, rp1, 1);
    rp1 += __shfl_xor_sync(0xffffffffu, rp1, 2);
    if ((lane & 3) == 0) {
        atomicAdd(&rsum[ar], rp0);
        atomicAdd(&rsum[ar + 8], rp1);
    }
    __syncthreads();

    const float inv0 = WSCALE_INV / (rsum[ar] + 1e-6f);
    const float inv1 = WSCALE_INV / (rsum[ar + 8] + 1e-6f);
#pragma unroll
    for (int nf = 0; nf < 4; nf++) {
        const int d = wn * 32 + nf * 8 + (lane & 3) * 2;
        __half* dst0 = out + (size_t)(b * T_ + q0 + ar) * C_ + h * DH + d;
        __half* dst1 = out + (size_t)(b * T_ + q0 + ar + 8) * C_ + h * DH + d;
        __half2 h0 = __floats2half2_rn(oacc[nf][0] * inv0, oacc[nf][1] * inv0);
        __half2 h1 = __floats2half2_rn(oacc[nf][2] * inv1, oacc[nf][3] * inv1);
        *(__half2*)dst0 = h0;
        *(__half2*)dst1 = h1;
    }
}

#define ATTN_SMEM ((6 * 64 * PST + 128) * 4)   // 55808 B

// ---------------------------------------------------------------------------
extern "C" void kernel_launch(void* const* d_in, const int* in_sizes, int n_in,
                              void* d_out, int out_size)
{
    const float* x   = (const float*)d_in[0];
    const float* Wq  = (const float*)d_in[2];
    const float* bq  = (const float*)d_in[3];
    const float* Wk  = (const float*)d_in[4];
    const float* bk  = (const float*)d_in[5];
    const float* Wv  = (const float*)d_in[6];
    const float* bv  = (const float*)d_in[7];
    const float* Wo  = (const float*)d_in[8];
    const float* bo  = (const float*)d_in[9];
    const float* rel = (const float*)d_in[10];

    __half *x2, *w2q, *w2k, *w2v, *w2o, *ath, *vth;
    unsigned *qhi, *qlo, *khi, *klo;
    cudaGetSymbolAddress((void**)&x2,  g_x2);
    cudaGetSymbolAddress((void**)&w2q, g_w2q);
    cudaGetSymbolAddress((void**)&w2k, g_w2k);
    cudaGetSymbolAddress((void**)&w2v, g_w2v);
    cudaGetSymbolAddress((void**)&w2o, g_w2o);
    cudaGetSymbolAddress((void**)&ath, g_ath);
    cudaGetSymbolAddress((void**)&vth, g_Vth);
    cudaGetSymbolAddress((void**)&qhi, g_Qhi);
    cudaGetSymbolAddress((void**)&qlo, g_Qlo);
    cudaGetSymbolAddress((void**)&khi, g_Khi);
    cudaGetSymbolAddress((void**)&klo, g_Klo);

    static int configured = 0;
    if (!configured) {
        cudaFuncSetAttribute(attn_v3, cudaFuncAttributeMaxDynamicSharedMemorySize,
                             ATTN_SMEM);
        cudaFuncSetAttribute(gemm_h2<0>, cudaFuncAttributeMaxDynamicSharedMemorySize,
                             GEMM_SMEM);
        cudaFuncSetAttribute(gemm_h2<2>, cudaFuncAttributeMaxDynamicSharedMemorySize,
                             GEMM_SMEM);
        cudaFuncSetAttribute(gemm_h2<3>, cudaFuncAttributeMaxDynamicSharedMemorySize,
                             GEMM_SMEM);
        configured = 1;
    }

    const int NX = B_ * T_ * C_, NW = C_ * C_;
    cvt_half<<<NX / 2048, 256>>>(x,  x2,  NX);
    cvt_half<<<NW / 2048, 256>>>(Wq, w2q, NW);
    cvt_half<<<NW / 2048, 256>>>(Wk, w2k, NW);
    cvt_half<<<NW / 2048, 256>>>(Wv, w2v, NW);
    cvt_half<<<NW / 2048, 256>>>(Wo, w2o, NW);

    dim3 gg(C_ / 128, (B_ * T_) / 128);  // (8, 32)
    gemm_h2<2><<<gg, 256, GEMM_SMEM>>>(x2, w2q, bq, nullptr, qhi, qlo, nullptr);
    gemm_h2<2><<<gg, 256, GEMM_SMEM>>>(x2, w2k, bk, nullptr, khi, klo, nullptr);
    gemm_h2<3><<<gg, 256, GEMM_SMEM>>>(x2, w2v, bv, nullptr, nullptr, nullptr, vth);

    attn_v3<<<dim3(16, H_, B_), 256, ATTN_SMEM>>>(qhi, qlo, khi, klo, vth, rel, ath);

    gemm_h2<0><<<gg, 256, GEMM_SMEM>>>(ath, w2o, bo, (float*)d_out, nullptr, nullptr, nullptr);
}

// round 11
// speedup vs baseline: 5.3407x; 1.1287x over previous
#include <cuda_runtime.h>
#include <cuda_bf16.h>
#include <cuda_fp16.h>
#include <cstdint>

// Problem constants (fixed by setup_inputs)
#define B_  4
#define T_  1024
#define C_  1024
#define H_  16
#define DH  64
#define MAXREL 32

// W-scale: keeps relu(..)+1e-6 weights inside fp16 normal range.
#define WSCALE 256.0f
#define WSCALE_INV (1.0f / 256.0f)

// Scratch (allocation-free rule: __device__ globals)
__device__ __half  g_x2 [B_*T_*C_];
__device__ __half  g_w2q[C_*C_], g_w2k[C_*C_], g_w2v[C_*C_], g_w2o[C_*C_];
__device__ __half  g_ath[B_*T_*C_];
__device__ __half  g_Vth[B_*H_*DH*T_];         // V half, [B,H,D,T]
__device__ unsigned g_Qhi[B_*H_*T_*DH/2], g_Qlo[B_*H_*T_*DH/2];  // bf16x2 pairs
__device__ unsigned g_Khi[B_*H_*T_*DH/2], g_Klo[B_*H_*T_*DH/2];

__device__ __forceinline__ uint32_t smem_u32(const void* p) {
    uint32_t a;
    asm("{ .reg .u64 t; cvta.to.shared.u64 t, %1; cvt.u32.u64 %0, t; }"
        : "=r"(a) : "l"(p));
    return a;
}

#define MMA_BF16(acc, a, b0, b1)                                              \
    asm volatile(                                                             \
        "mma.sync.aligned.m16n8k16.row.col.f32.bf16.bf16.f32 "                \
        "{%0,%1,%2,%3}, {%4,%5,%6,%7}, {%8,%9}, {%0,%1,%2,%3};"               \
        : "+f"(acc[0]), "+f"(acc[1]), "+f"(acc[2]), "+f"(acc[3])              \
        : "r"(a[0]), "r"(a[1]), "r"(a[2]), "r"(a[3]), "r"(b0), "r"(b1))

#define MMA_FP16(acc, a, b0, b1)                                              \
    asm volatile(                                                             \
        "mma.sync.aligned.m16n8k16.row.col.f32.f16.f16.f32 "                  \
        "{%0,%1,%2,%3}, {%4,%5,%6,%7}, {%8,%9}, {%0,%1,%2,%3};"               \
        : "+f"(acc[0]), "+f"(acc[1]), "+f"(acc[2]), "+f"(acc[3])              \
        : "r"(a[0]), "r"(a[1]), "r"(a[2]), "r"(a[3]), "r"(b0), "r"(b1))

#define LDSM_X4(r0, r1, r2, r3, addr)                                         \
    asm volatile("ldmatrix.sync.aligned.m8n8.x4.shared.b16 {%0,%1,%2,%3}, [%4];" \
        : "=r"(r0), "=r"(r1), "=r"(r2), "=r"(r3) : "r"(addr))

#define CP_ASYNC16(saddr, gptr)                                               \
    asm volatile("cp.async.cg.shared.global [%0], [%1], 16;"                  \
                 :: "r"(saddr), "l"(gptr) : "memory")
#define CP_COMMIT()      asm volatile("cp.async.commit_group;" ::: "memory")
#define CP_WAIT(n)       asm volatile("cp.async.wait_group %0;" :: "n"(n) : "memory")

// ---------------------------------------------------------------------------
// f32 -> half conversion. blockIdx.y selects among up to 4 arrays.
// ---------------------------------------------------------------------------
__global__ void cvt_half4(const float* __restrict__ i0, __half* __restrict__ o0,
                          const float* __restrict__ i1, __half* __restrict__ o1,
                          const float* __restrict__ i2, __half* __restrict__ o2,
                          const float* __restrict__ i3, __half* __restrict__ o3,
                          int n)
{
    const float* in  = blockIdx.y == 0 ? i0 : blockIdx.y == 1 ? i1
                     : blockIdx.y == 2 ? i2 : i3;
    __half* out      = blockIdx.y == 0 ? o0 : blockIdx.y == 1 ? o1
                     : blockIdx.y == 2 ? o2 : o3;
    const int i = (blockIdx.x * blockDim.x + threadIdx.x) * 8;
    if (i >= n) return;
    float4 v0 = *(const float4*)(in + i);
    float4 v1 = *(const float4*)(in + i + 4);
    __half2 h[4] = {__floats2half2_rn(v0.x, v0.y), __floats2half2_rn(v0.z, v0.w),
                    __floats2half2_rn(v1.x, v1.y), __floats2half2_rn(v1.z, v1.w)};
    *(uint4*)(out + i) = *(uint4*)h;
}
__global__ void cvt_half(const float* __restrict__ in, __half* __restrict__ out,
                         int n)
{
    const int i = (blockIdx.x * blockDim.x + threadIdx.x) * 8;
    if (i >= n) return;
    float4 v0 = *(const float4*)(in + i);
    float4 v1 = *(const float4*)(in + i + 4);
    __half2 h[4] = {__floats2half2_rn(v0.x, v0.y), __floats2half2_rn(v0.z, v0.w),
                    __floats2half2_rn(v1.x, v1.y), __floats2half2_rn(v1.z, v1.w)};
    *(uint4*)(out + i) = *(uint4*)h;
}

// ---------------------------------------------------------------------------
// fp16 GEMM, cp.async 3-stage, ldmatrix fragment loads.
// C = A[M,K] @ W[N,K]^T + bias[N]. BM=BN=128, BK=32, 256 thr (8 warps 2x4).
// MODE 0: C row-major [M,N] fp32
// MODE 2: packed bf16 hi/lo pairs out, [B,H,T,DH/2]   (Q, K)
// MODE 3: half out, transposed [B,H,DH,T]             (V)
// ---------------------------------------------------------------------------
#define GST   20
#define STG_U (128 * GST)
#define GEMM_SMEM (3 * 2 * STG_U * 4)   // 61440 B

__device__ __forceinline__ void store_hilo(unsigned* Phi, unsigned* Plo, size_t off,
                                           float x, float y) {
    __nv_bfloat16 hx = __float2bfloat16(x), hy = __float2bfloat16(y);
    __nv_bfloat162 h2(hx, hy);
    __nv_bfloat162 l2(__float2bfloat16(x - __bfloat162float(hx)),
                      __float2bfloat16(y - __bfloat162float(hy)));
    Phi[off] = *(unsigned*)&h2;
    Plo[off] = *(unsigned*)&l2;
}

template<int MODE>
__global__ void __launch_bounds__(256, 2)
gemm_h2(const __half* __restrict__ A, const __half* __restrict__ W,
        const float* __restrict__ bias, float* __restrict__ C,
        unsigned* __restrict__ Phi, unsigned* __restrict__ Plo,
        __half* __restrict__ Vh)
{
    const int K = 1024, N = 1024;
    extern __shared__ unsigned sm[];

    const int t = threadIdx.x;
    const int lane = t & 31, warp = t >> 5;
    const int wm = warp >> 2, wn = warp & 3;
    const int m0 = blockIdx.y * 128, n0 = blockIdx.x * 128;

    // ldmatrix lane decomposition
    const int lrow = lane & 7;
    const int agrp_r = ((lane >> 3) & 1) * 8;      // A: row +0/+8
    const int agrp_c = ((lane >> 4) & 1) * 4;      // A: col +0/+4 (k lo/hi)
    const int bgrp_r = ((lane >> 4) & 1) * 8;      // B: second matrix of pair
    const int bgrp_c = ((lane >> 3) & 1) * 4;      // B: col +0/+4

    const int r   = t >> 1;
    const int seg = t & 1;
    const __half* Ap = A + (size_t)(m0 + r) * K + seg * 16;
    const __half* Wp = W + (size_t)(n0 + r) * K + seg * 16;
    const uint32_t smbase = smem_u32(sm);
    const uint32_t dstA = smbase + (r * GST + seg * 8) * 4;
    const uint32_t dstB = dstA + STG_U * 4;

    auto issue = [&](int kt) {
        const uint32_t sb = (kt % 3) * (2 * STG_U * 4);
        const __half* a = Ap + kt * 32;
        const __half* b = Wp + kt * 32;
        CP_ASYNC16(dstA + sb,      a);
        CP_ASYNC16(dstA + sb + 16, a + 8);
        CP_ASYNC16(dstB + sb,      b);
        CP_ASYNC16(dstB + sb + 16, b + 8);
        CP_COMMIT();
    };

    float acc[4][4][4];
#pragma unroll
    for (int i = 0; i < 4; i++)
#pragma unroll
        for (int j = 0; j < 4; j++)
#pragma unroll
            for (int x = 0; x < 4; x++) acc[i][j][x] = 0.f;

    issue(0);
    issue(1);

    const int NKT = K / 32;   // 32
    for (int kt = 0; kt < NKT; kt++) {
        CP_WAIT(1);
        __syncthreads();

        const uint32_t sa = smbase + (kt % 3) * 2 * STG_U * 4;
        const uint32_t sb = sa + STG_U * 4;
#pragma unroll
        for (int s = 0; s < 2; s++) {
            const int g0 = s * 8;
            unsigned af[4][4], bf[4][2];
#pragma unroll
            for (int mf = 0; mf < 4; mf++) {
                const int rr = wm * 64 + mf * 16 + agrp_r + lrow;
                LDSM_X4(af[mf][0], af[mf][1], af[mf][2], af[mf][3],
                        sa + (rr * GST + g0 + agrp_c) * 4);
            }
#pragma unroll
            for (int np = 0; np < 2; np++) {
                const int rr = wn * 32 + (np * 2) * 8 + bgrp_r + lrow;
                LDSM_X4(bf[np*2][0], bf[np*2][1], bf[np*2+1][0], bf[np*2+1][1],
                        sb + (rr * GST + g0 + bgrp_c) * 4);
            }
#pragma unroll
            for (int mf = 0; mf < 4; mf++)
#pragma unroll
                for (int nf = 0; nf < 4; nf++)
                    MMA_FP16(acc[mf][nf], af[mf], bf[nf][0], bf[nf][1]);
        }
        if (kt + 2 < NKT) issue(kt + 2);
    }

    // epilogue
#pragma unroll
    for (int nf = 0; nf < 4; nf++) {
        const int col = n0 + wn * 32 + nf * 8 + (lane & 3) * 2;
        const float bv0 = bias[col], bv1 = bias[col + 1];
#pragma unroll
        for (int mf = 0; mf < 4; mf++) {
            const int row = m0 + wm * 64 + mf * 16 + (lane >> 2);
            float2 v0 = make_float2(acc[mf][nf][0] + bv0, acc[mf][nf][1] + bv1);
            float2 v1 = make_float2(acc[mf][nf][2] + bv0, acc[mf][nf][3] + bv1);
            if (MODE == 0) {
                *(float2*)(C + (size_t)row * N + col)       = v0;
                *(float2*)(C + (size_t)(row + 8) * N + col) = v1;
            } else if (MODE == 2) {
                const int h = col >> 6, d = col & 63, pr = d >> 1;
                const int bb = row >> 10, tt = row & 1023;
                const size_t off = ((((size_t)bb * H_ + h) * T_ + tt) * 32) + pr;
                store_hilo(Phi, Plo, off,          v0.x, v0.y);
                store_hilo(Phi, Plo, off + 8 * 32, v1.x, v1.y);
            } else {  // MODE 3: V half, transposed [B,H,D,T]
                const int h = col >> 6, d = col & 63;
                const int bb = row >> 10, tt = row & 1023;
                const size_t vb = (((size_t)bb * H_ + h) * DH + d) * T_ + tt;
                Vh[vb]          = __float2half(v0.x);
                Vh[vb + T_]     = __float2half(v0.y);
                Vh[vb + 8]      = __float2half(v1.x);
                Vh[vb + T_ + 8] = __float2half(v1.y);
            }
        }
    }
}

// ---------------------------------------------------------------------------
// Fused causal algebraic attention v4: ldmatrix fragment loads.
//   Stage1: S = Q @ K^T, bf16 hi/lo 3-term k16
//   Stage2: O += (S*W) @ V, fp16 k16; normalization folds 1/S.
// ---------------------------------------------------------------------------
#define PST 36

__global__ void __launch_bounds__(256, 3)
attn_v4(const unsigned* __restrict__ Qhi, const unsigned* __restrict__ Qlo,
        const unsigned* __restrict__ Khi, const unsigned* __restrict__ Klo,
        const __half* __restrict__ Vtg, const float* __restrict__ rel_bias,
        __half* __restrict__ out)
{
    extern __shared__ unsigned sm[];
    unsigned* Qh_s = sm;
    unsigned* Ql_s = Qh_s + 64 * PST;
    unsigned* Kh_s = Ql_s + 64 * PST;
    unsigned* Kl_s = Kh_s + 64 * PST;
    unsigned* Vt_s = Kl_s + 64 * PST;
    unsigned* Ws_s = Vt_s + 64 * PST;
    float* bh   = (float*)(Ws_s + 64 * PST);
    float* rsum = bh + 64;

    const int qt = 15 - (int)blockIdx.x;
    const int h  = blockIdx.y;
    const int b  = blockIdx.z;
    const int t  = threadIdx.x;
    const int lane = t & 31, warp = t >> 5;
    const int wm = warp >> 1, wn = warp & 1;
    const int q0 = qt * 64;
    const int bhx = b * H_ + h;

    // ldmatrix lane decomposition
    const int lrow = lane & 7;
    const int agrp_r = ((lane >> 3) & 1) * 8;
    const int agrp_c = ((lane >> 4) & 1) * 4;
    const int bgrp_r = ((lane >> 4) & 1) * 8;
    const int bgrp_c = ((lane >> 3) & 1) * 4;

    const uint32_t qh_b = smem_u32(Qh_s), ql_b = smem_u32(Ql_s);
    const uint32_t kh_b = smem_u32(Kh_s), kl_b = smem_u32(Kl_s);
    const uint32_t vt_b = smem_u32(Vt_s), ws_b = smem_u32(Ws_s);

    const int r4  = t >> 2;
    const int cp8 = (t & 3) * 8;

    {
        const size_t qoff = ((size_t)bhx * T_ + q0 + r4) * 32 + cp8;
        CP_ASYNC16(smem_u32(&Qh_s[r4 * PST + cp8]),     Qhi + qoff);
        CP_ASYNC16(smem_u32(&Qh_s[r4 * PST + cp8 + 4]), Qhi + qoff + 4);
        CP_ASYNC16(smem_u32(&Ql_s[r4 * PST + cp8]),     Qlo + qoff);
        CP_ASYNC16(smem_u32(&Ql_s[r4 * PST + cp8 + 4]), Qlo + qoff + 4);
        CP_COMMIT();
    }
    if (t < 2 * MAXREL - 1) bh[t] = rel_bias[t * H_ + h];
    if (t < 64) rsum[t] = 0.f;

    const unsigned* Khg = Khi + (size_t)bhx * T_ * 32;
    const unsigned* Klg = Klo + (size_t)bhx * T_ * 32;
    const __half*   Vbg = Vtg + (size_t)bhx * DH * T_;

    float oacc[4][4];
#pragma unroll
    for (int i = 0; i < 4; i++)
#pragma unroll
        for (int j = 0; j < 4; j++) oacc[i][j] = 0.f;
    float rp0 = 0.f, rp1 = 0.f;

    const int ar = wm * 16 + (lane >> 2);

    for (int kt = 0; kt <= qt; kt++) {
        const int k0 = kt * 64;
        __syncthreads();

        {
            const size_t koff = (size_t)(k0 + r4) * 32 + cp8;
            CP_ASYNC16(smem_u32(&Kh_s[r4 * PST + cp8]),     Khg + koff);
            CP_ASYNC16(smem_u32(&Kh_s[r4 * PST + cp8 + 4]), Khg + koff + 4);
            CP_ASYNC16(smem_u32(&Kl_s[r4 * PST + cp8]),     Klg + koff);
            CP_ASYNC16(smem_u32(&Kl_s[r4 * PST + cp8 + 4]), Klg + koff + 4);
            CP_COMMIT();
            const __half* vp = Vbg + (size_t)r4 * T_ + k0 + (t & 3) * 16;
            CP_ASYNC16(smem_u32(&Vt_s[r4 * PST + cp8]),     vp);
            CP_ASYNC16(smem_u32(&Vt_s[r4 * PST + cp8 + 4]), vp + 8);
            CP_COMMIT();
        }
        CP_WAIT(1);
        __syncthreads();

        // Stage 1: bf16 3-term
        float s[4][4];
#pragma unroll
        for (int i = 0; i < 4; i++)
#pragma unroll
            for (int j = 0; j < 4; j++) s[i][j] = 0.f;

#pragma unroll
        for (int st = 0; st < 4; st++) {
            const int g0 = st * 8;
            unsigned ah[4], al[4], bhf[4][2], blf[4][2];
            {
                const int rr = wm * 16 + agrp_r + lrow;
                LDSM_X4(ah[0], ah[1], ah[2], ah[3],
                        qh_b + (rr * PST + g0 + agrp_c) * 4);
                LDSM_X4(al[0], al[1], al[2], al[3],
                        ql_b + (rr * PST + g0 + agrp_c) * 4);
            }
#pragma unroll
            for (int np = 0; np < 2; np++) {
                const int rr = wn * 32 + (np * 2) * 8 + bgrp_r + lrow;
                LDSM_X4(bhf[np*2][0], bhf[np*2][1], bhf[np*2+1][0], bhf[np*2+1][1],
                        kh_b + (rr * PST + g0 + bgrp_c) * 4);
                LDSM_X4(blf[np*2][0], blf[np*2][1], blf[np*2+1][0], blf[np*2+1][1],
                        kl_b + (rr * PST + g0 + bgrp_c) * 4);
            }
#pragma unroll
            for (int nf = 0; nf < 4; nf++) {
                MMA_BF16(s[nf], ah, bhf[nf][0], bhf[nf][1]);
                MMA_BF16(s[nf], ah, blf[nf][0], blf[nf][1]);
                MMA_BF16(s[nf], al, bhf[nf][0], bhf[nf][1]);
            }
        }

        // Epilogue -> W (half, scaled) + rsum (unscaled, fp32)
        {
            const int qg0 = q0 + ar;
            const bool diag = (kt == qt);
#pragma unroll
            for (int nf = 0; nf < 4; nf++) {
                const int kg0 = k0 + wn * 32 + nf * 8 + (lane & 3) * 2;
                float w[4];
#pragma unroll
                for (int c = 0; c < 4; c++) {
                    const int qg = qg0 + (c >> 1) * 8;
                    const int kg = kg0 + (c & 1);
                    const int rel = kg - qg;
                    float wv = 0.f;
                    if (!diag || rel <= 0) {
                        const int u = max(rel + (MAXREL - 1), 0);
                        wv = fmaxf(fmaf(s[nf][c], 0.125f, bh[u]), 0.f) + 1e-6f;
                    }
                    w[c] = wv;
                }
                rp0 += w[0] + w[1];
                rp1 += w[2] + w[3];
                const int pc = wn * 16 + nf * 4 + (lane & 3);
                __half2 h0 = __floats2half2_rn(w[0] * WSCALE, w[1] * WSCALE);
                __half2 h1 = __floats2half2_rn(w[2] * WSCALE, w[3] * WSCALE);
                Ws_s[ar * PST + pc]       = *(unsigned*)&h0;
                Ws_s[(ar + 8) * PST + pc] = *(unsigned*)&h1;
            }
        }
        CP_WAIT(0);
        __syncthreads();

        // Stage 2: O += W @ V, fp16 k16
#pragma unroll
        for (int st = 0; st < 4; st++) {
            const int g0 = st * 8;
            unsigned a[4], bf[4][2];
            {
                const int rr = wm * 16 + agrp_r + lrow;
                LDSM_X4(a[0], a[1], a[2], a[3],
                        ws_b + (rr * PST + g0 + agrp_c) * 4);
            }
#pragma unroll
            for (int np = 0; np < 2; np++) {
                const int rr = wn * 32 + (np * 2) * 8 + bgrp_r + lrow;
                LDSM_X4(bf[np*2][0], bf[np*2][1], bf[np*2+1][0], bf[np*2+1][1],
                        vt_b + (rr * PST + g0 + bgrp_c) * 4);
            }
#pragma unroll
            for (int nf = 0; nf < 4; nf++)
                MMA_FP16(oacc[nf], a, bf[nf][0], bf[nf][1]);
        }
    }

    rp0 += __shfl_xor_sync(0xffffffffu, rp0, 1);
    rp0 += __shfl_xor_sync(0xffffffffu, rp0, 2);
    rp1 += __shfl_xor_sync(0xffffffffu, rp1, 1);
    rp1 += __shfl_xor_sync(0xffffffffu, rp1, 2);
    if ((lane & 3) == 0) {
        atomicAdd(&rsum[ar], rp0);
        atomicAdd(&rsum[ar + 8], rp1);
    }
    __syncthreads();

    const float inv0 = WSCALE_INV / (rsum[ar] + 1e-6f);
    const float inv1 = WSCALE_INV / (rsum[ar + 8] + 1e-6f);
#pragma unroll
    for (int nf = 0; nf < 4; nf++) {
        const int d = wn * 32 + nf * 8 + (lane & 3) * 2;
        __half* dst0 = out + (size_t)(b * T_ + q0 + ar) * C_ + h * DH + d;
        __half* dst1 = out + (size_t)(b * T_ + q0 + ar + 8) * C_ + h * DH + d;
        __half2 h0 = __floats2half2_rn(oacc[nf][0] * inv0, oacc[nf][1] * inv0);
        __half2 h1 = __floats2half2_rn(oacc[nf][2] * inv1, oacc[nf][3] * inv1);
        *(__half2*)dst0 = h0;
        *(__half2*)dst1 = h1;
    }
}

#define ATTN_SMEM ((6 * 64 * PST + 128) * 4)   // 55808 B

// ---------------------------------------------------------------------------
extern "C" void kernel_launch(void* const* d_in, const int* in_sizes, int n_in,
                              void* d_out, int out_size)
{
    const float* x   = (const float*)d_in[0];
    const float* Wq  = (const float*)d_in[2];
    const float* bq  = (const float*)d_in[3];
    const float* Wk  = (const float*)d_in[4];
    const float* bk  = (const float*)d_in[5];
    const float* Wv  = (const float*)d_in[6];
    const float* bv  = (const float*)d_in[7];
    const float* Wo  = (const float*)d_in[8];
    const float* bo  = (const float*)d_in[9];
    const float* rel = (const float*)d_in[10];

    __half *x2, *w2q, *w2k, *w2v, *w2o, *ath, *vth;
    unsigned *qhi, *qlo, *khi, *klo;
    cudaGetSymbolAddress((void**)&x2,  g_x2);
    cudaGetSymbolAddress((void**)&w2q, g_w2q);
    cudaGetSymbolAddress((void**)&w2k, g_w2k);
    cudaGetSymbolAddress((void**)&w2v, g_w2v);
    cudaGetSymbolAddress((void**)&w2o, g_w2o);
    cudaGetSymbolAddress((void**)&ath, g_ath);
    cudaGetSymbolAddress((void**)&vth, g_Vth);
    cudaGetSymbolAddress((void**)&qhi, g_Qhi);
    cudaGetSymbolAddress((void**)&qlo, g_Qlo);
    cudaGetSymbolAddress((void**)&khi, g_Khi);
    cudaGetSymbolAddress((void**)&klo, g_Klo);

    static int configured = 0;
    if (!configured) {
        cudaFuncSetAttribute(attn_v4, cudaFuncAttributeMaxDynamicSharedMemorySize,
                             ATTN_SMEM);
        cudaFuncSetAttribute(gemm_h2<0>, cudaFuncAttributeMaxDynamicSharedMemorySize,
                             GEMM_SMEM);
        cudaFuncSetAttribute(gemm_h2<2>, cudaFuncAttributeMaxDynamicSharedMemorySize,
                             GEMM_SMEM);
        cudaFuncSetAttribute(gemm_h2<3>, cudaFuncAttributeMaxDynamicSharedMemorySize,
                             GEMM_SMEM);
        configured = 1;
    }

    const int NX = B_ * T_ * C_, NW = C_ * C_;
    // weights: one fused launch (4 arrays); x: separate (different size)
    cvt_half4<<<dim3(NW / 2048, 4), 256>>>(Wq, w2q, Wk, w2k, Wv, w2v, Wo, w2o, NW);
    cvt_half<<<NX / 2048, 256>>>(x, x2, NX);

    dim3 gg(C_ / 128, (B_ * T_) / 128);  // (8, 32)
    gemm_h2<2><<<gg, 256, GEMM_SMEM>>>(x2, w2q, bq, nullptr, qhi, qlo, nullptr);
    gemm_h2<2><<<gg, 256, GEMM_SMEM>>>(x2, w2k, bk, nullptr, khi, klo, nullptr);
    gemm_h2<3><<<gg, 256, GEMM_SMEM>>>(x2, w2v, bv, nullptr, nullptr, nullptr, vth);

    attn_v4<<<dim3(16, H_, B_), 256, ATTN_SMEM>>>(qhi, qlo, khi, klo, vth, rel, ath);

    gemm_h2<0><<<gg, 256, GEMM_SMEM>>>(ath, w2o, bo, (float*)d_out, nullptr, nullptr, nullptr);
}